// round 1
// baseline (speedup 1.0000x reference)
#include <cuda_runtime.h>
#include <math.h>

#define NH   16
#define NKV  4
#define HD   128
#define SMAX 2048

// Scratch (device globals — no allocation allowed)
__device__ float g_Q[SMAX * NH * HD];
__device__ float g_K[SMAX * NKV * HD];
__device__ float g_V[SMAX * NKV * HD];
__device__ float g_A[SMAX * NH * HD];

// ---------------------------------------------------------------------------
// SGEMM: C[M,N] = A[M,K] @ B[K,N], all row-major fp32.
// BM=128, BN=128, BK=16, 256 threads, 8x8 per-thread micro-tile.
// All shapes here are multiples of the tiles (M=2048, N in {2048,512}, K=2048).
// ---------------------------------------------------------------------------
#define GBM 128
#define GBN 128
#define GBK 16

__global__ __launch_bounds__(256) void sgemm_kernel(
    const float* __restrict__ A, const float* __restrict__ B,
    float* __restrict__ C, int M, int N, int K)
{
    __shared__ float As[GBK][GBM + 4];   // A tile transposed, padded
    __shared__ float Bs[GBK][GBN];

    const int tid = threadIdx.x;
    const int tx = tid & 15;     // 0..15 -> N
    const int ty = tid >> 4;     // 0..15 -> M
    const int bm0 = blockIdx.y * GBM;
    const int bn0 = blockIdx.x * GBN;

    float acc[8][8];
#pragma unroll
    for (int i = 0; i < 8; i++)
#pragma unroll
        for (int j = 0; j < 8; j++) acc[i][j] = 0.f;

    for (int k0 = 0; k0 < K; k0 += GBK) {
        // Load A tile (128 x 16), transpose into As
#pragma unroll
        for (int it = 0; it < 2; it++) {
            int idx = tid + it * 256;          // 0..511
            int row = idx >> 2;                // 0..127
            int c4  = (idx & 3) * 4;           // 0,4,8,12
            float4 v = *(const float4*)(A + (size_t)(bm0 + row) * K + k0 + c4);
            As[c4 + 0][row] = v.x;
            As[c4 + 1][row] = v.y;
            As[c4 + 2][row] = v.z;
            As[c4 + 3][row] = v.w;
        }
        // Load B tile (16 x 128)
#pragma unroll
        for (int it = 0; it < 2; it++) {
            int idx = tid + it * 256;
            int row = idx >> 5;                // 0..15
            int c4  = (idx & 31) * 4;          // 0..124
            *(float4*)(&Bs[row][c4]) =
                *(const float4*)(B + (size_t)(k0 + row) * N + bn0 + c4);
        }
        __syncthreads();

#pragma unroll
        for (int kk = 0; kk < GBK; kk++) {
            float ra[8], rb[8];
            *(float4*)(&ra[0]) = *(const float4*)(&As[kk][ty * 8]);
            *(float4*)(&ra[4]) = *(const float4*)(&As[kk][ty * 8 + 4]);
            *(float4*)(&rb[0]) = *(const float4*)(&Bs[kk][tx * 8]);
            *(float4*)(&rb[4]) = *(const float4*)(&Bs[kk][tx * 8 + 4]);
#pragma unroll
            for (int i = 0; i < 8; i++)
#pragma unroll
                for (int j = 0; j < 8; j++)
                    acc[i][j] += ra[i] * rb[j];
        }
        __syncthreads();
    }

#pragma unroll
    for (int i = 0; i < 8; i++) {
        float* dst = C + (size_t)(bm0 + ty * 8 + i) * N + bn0 + tx * 8;
        *(float4*)(dst)     = make_float4(acc[i][0], acc[i][1], acc[i][2], acc[i][3]);
        *(float4*)(dst + 4) = make_float4(acc[i][4], acc[i][5], acc[i][6], acc[i][7]);
    }
}

// ---------------------------------------------------------------------------
// RoPE in-place. X: [S][nh][128]; interleaved pairs (even, odd).
// ---------------------------------------------------------------------------
__global__ void rope_kernel(float* __restrict__ X, const int* __restrict__ pos,
                            int S, int nh)
{
    int idx = blockIdx.x * blockDim.x + threadIdx.x;
    int total = S * nh * (HD / 2);
    if (idx >= total) return;
    int i  = idx & 63;            // pair index 0..63
    int sh = idx >> 6;            // s*nh + h
    int s  = sh / nh;

    // freq = 10000^(-2i/128) computed as exp2f
    float e = -(float)(2 * i) * (1.0f / 128.0f) * 13.287712379549449f; // log2(1e4)
    float freq = exp2f(e);
    float ang = (float)pos[s] * freq;
    float sn, cs;
    sincosf(ang, &sn, &cs);

    float2* p = (float2*)(X + (size_t)idx * 2);
    float2 v = *p;
    float o0 = v.x * cs - v.y * sn;
    float o1 = v.x * sn + v.y * cs;
    *p = make_float2(o0, o1);
}

// ---------------------------------------------------------------------------
// Flash attention, fp32, causal + padding + segment masks, GQA (kv = h/4).
// Block: 512 threads, BQ=128 query rows, BKT=64 key rows per inner tile.
// Thread (tx 0..15, ty 0..31): S-tile 4x4, O-tile 4 rows x 8 cols.
// Q, K stored transposed in smem ([d][row]) for conflict-free dot loops.
// ---------------------------------------------------------------------------
#define BQ   128
#define BKT  64
#define QSTR 132   // padded stride for Qst (mult of 4 for float4 alignment)
#define KSTR 68    // padded stride for Kst

__global__ __launch_bounds__(512, 1) void attn_kernel(
    const float* __restrict__ Q, const float* __restrict__ K,
    const float* __restrict__ V,
    const int* __restrict__ amask, const int* __restrict__ segs,
    float* __restrict__ O, int S)
{
    extern __shared__ float sm[];
    float* Qst  = sm;                      // [HD][QSTR]
    float* Kst  = Qst + HD * QSTR;         // [HD][KSTR]
    float* Vs   = Kst + HD * KSTR;         // [BKT][HD]
    float* Ps   = Vs + BKT * HD;           // [BQ][BKT]
    float* kinv = Ps + BQ * BKT;           // [BKT]  0 = valid
    int*   kseg = (int*)(kinv + BKT);      // [BKT]

    const int tid = threadIdx.x;
    const int tx = tid & 15;
    const int ty = tid >> 4;
    const int h  = blockIdx.y;
    const int q0 = blockIdx.x * BQ;
    const int kvh = h >> 2;                // h / (NH/NKV)
    const float scale = 0.0883883476483184f; // 1/sqrt(128)

    // Load Q tile (scaled) into transposed smem
#pragma unroll
    for (int it = 0; it < 8; it++) {
        int idx = tid + it * 512;          // 0..4095
        int row = idx >> 5;                // 0..127
        int d4  = (idx & 31) * 4;
        float4 v = *(const float4*)(Q + ((size_t)(q0 + row) * NH + h) * HD + d4);
        Qst[(d4 + 0) * QSTR + row] = v.x * scale;
        Qst[(d4 + 1) * QSTR + row] = v.y * scale;
        Qst[(d4 + 2) * QSTR + row] = v.z * scale;
        Qst[(d4 + 3) * QSTR + row] = v.w * scale;
    }

    float m_i[4], l_i[4], acc[4][8];
#pragma unroll
    for (int i = 0; i < 4; i++) {
        m_i[i] = -1e30f;
        l_i[i] = 0.f;
#pragma unroll
        for (int j = 0; j < 8; j++) acc[i][j] = 0.f;
    }
    int qpos[4], qseg[4];
#pragma unroll
    for (int i = 0; i < 4; i++) {
        qpos[i] = q0 + ty * 4 + i;
        qseg[i] = segs[qpos[i]];
    }

    const int kend = q0 + BQ;              // causal upper bound (exclusive)
    for (int k0 = 0; k0 < kend; k0 += BKT) {
        __syncthreads();   // previous-iteration consumers done with Kst/Vs

        // Load K (transposed) and V tiles
#pragma unroll
        for (int it = 0; it < 4; it++) {
            int idx = tid + it * 512;      // 0..2047
            int row = idx >> 5;            // 0..63
            int d4  = (idx & 31) * 4;
            float4 kv = *(const float4*)(K + ((size_t)(k0 + row) * NKV + kvh) * HD + d4);
            Kst[(d4 + 0) * KSTR + row] = kv.x;
            Kst[(d4 + 1) * KSTR + row] = kv.y;
            Kst[(d4 + 2) * KSTR + row] = kv.z;
            Kst[(d4 + 3) * KSTR + row] = kv.w;
            float4 vv = *(const float4*)(V + ((size_t)(k0 + row) * NKV + kvh) * HD + d4);
            *(float4*)(Vs + row * HD + d4) = vv;
        }
        if (tid < BKT) {
            kinv[tid] = (amask[k0 + tid] > 0) ? 0.f : 1.f;
            kseg[tid] = segs[k0 + tid];
        }
        __syncthreads();

        // S = (Q*scale) K^T  (4x4 per thread)
        float s[4][4];
#pragma unroll
        for (int i = 0; i < 4; i++)
#pragma unroll
            for (int j = 0; j < 4; j++) s[i][j] = 0.f;

#pragma unroll 16
        for (int d = 0; d < HD; d++) {
            float4 qv = *(const float4*)(Qst + d * QSTR + ty * 4);
            float4 kv = *(const float4*)(Kst + d * KSTR + tx * 4);
            float qa[4] = {qv.x, qv.y, qv.z, qv.w};
            float ka[4] = {kv.x, kv.y, kv.z, kv.w};
#pragma unroll
            for (int i = 0; i < 4; i++)
#pragma unroll
                for (int j = 0; j < 4; j++)
                    s[i][j] += qa[i] * ka[j];
        }

        // Mask
        float kin[4]; int ksg[4];
#pragma unroll
        for (int j = 0; j < 4; j++) {
            kin[j] = kinv[tx * 4 + j];
            ksg[j] = kseg[tx * 4 + j];
        }
#pragma unroll
        for (int i = 0; i < 4; i++)
#pragma unroll
            for (int j = 0; j < 4; j++) {
                int kp = k0 + tx * 4 + j;
                bool ok = (kp <= qpos[i]) && (kin[j] == 0.f) && (ksg[j] == qseg[i]);
                if (!ok) s[i][j] = -INFINITY;
            }

        // Online softmax update (row reductions across the 16-lane tx group)
#pragma unroll
        for (int i = 0; i < 4; i++) {
            float mx = fmaxf(fmaxf(s[i][0], s[i][1]), fmaxf(s[i][2], s[i][3]));
#pragma unroll
            for (int o = 1; o < 16; o <<= 1)
                mx = fmaxf(mx, __shfl_xor_sync(0xffffffffu, mx, o));
            float mnew = fmaxf(m_i[i], mx);
            float alpha = __expf(m_i[i] - mnew);
            m_i[i] = mnew;
            float p0 = __expf(s[i][0] - mnew);
            float p1 = __expf(s[i][1] - mnew);
            float p2 = __expf(s[i][2] - mnew);
            float p3 = __expf(s[i][3] - mnew);
            *(float4*)(Ps + (ty * 4 + i) * BKT + tx * 4) = make_float4(p0, p1, p2, p3);
            float ps = p0 + p1 + p2 + p3;
#pragma unroll
            for (int o = 1; o < 16; o <<= 1)
                ps += __shfl_xor_sync(0xffffffffu, ps, o);
            l_i[i] = l_i[i] * alpha + ps;
#pragma unroll
            for (int j = 0; j < 8; j++) acc[i][j] *= alpha;
        }
        __syncthreads();

        // O += P @ V
#pragma unroll 8
        for (int kk = 0; kk < BKT; kk++) {
            float4 v0 = *(const float4*)(Vs + kk * HD + tx * 8);
            float4 v1 = *(const float4*)(Vs + kk * HD + tx * 8 + 4);
            float vv[8] = {v0.x, v0.y, v0.z, v0.w, v1.x, v1.y, v1.z, v1.w};
#pragma unroll
            for (int i = 0; i < 4; i++) {
                float p = Ps[(ty * 4 + i) * BKT + kk];
#pragma unroll
                for (int j = 0; j < 8; j++)
                    acc[i][j] += p * vv[j];
            }
        }
    }

    // Epilogue: normalize and write [S][NH][HD]
#pragma unroll
    for (int i = 0; i < 4; i++) {
        float inv = (l_i[i] > 0.f) ? (1.0f / l_i[i]) : 0.f;
        float* dst = O + ((size_t)qpos[i] * NH + h) * HD + tx * 8;
        *(float4*)(dst)     = make_float4(acc[i][0] * inv, acc[i][1] * inv,
                                          acc[i][2] * inv, acc[i][3] * inv);
        *(float4*)(dst + 4) = make_float4(acc[i][4] * inv, acc[i][5] * inv,
                                          acc[i][6] * inv, acc[i][7] * inv);
    }
}

// ---------------------------------------------------------------------------
// Host launcher
// ---------------------------------------------------------------------------
extern "C" void kernel_launch(void* const* d_in, const int* in_sizes, int n_in,
                              void* d_out, int out_size)
{
    const float* X     = (const float*)d_in[0];
    const int*   amask = (const int*)d_in[1];
    const int*   segs  = (const int*)d_in[2];
    const int*   pos   = (const int*)d_in[3];
    const float* Wq    = (const float*)d_in[4];
    const float* Wk    = (const float*)d_in[5];
    const float* Wv    = (const float*)d_in[6];
    const float* Wo    = (const float*)d_in[7];
    float* out = (float*)d_out;

    const int S   = in_sizes[3];            // B=1
    const int H   = in_sizes[0] / S;        // 2048
    const int Hkv = in_sizes[5] / H;        // 512

    float *Qd, *Kd, *Vd, *Ad;
    cudaGetSymbolAddress((void**)&Qd, g_Q);
    cudaGetSymbolAddress((void**)&Kd, g_K);
    cudaGetSymbolAddress((void**)&Vd, g_V);
    cudaGetSymbolAddress((void**)&Ad, g_A);

    // Projections
    sgemm_kernel<<<dim3(H / GBN,   S / GBM), 256>>>(X, Wq, Qd, S, H,   H);
    sgemm_kernel<<<dim3(Hkv / GBN, S / GBM), 256>>>(X, Wk, Kd, S, Hkv, H);
    sgemm_kernel<<<dim3(Hkv / GBN, S / GBM), 256>>>(X, Wv, Vd, S, Hkv, H);

    // RoPE
    int ntq = S * NH  * (HD / 2);
    int ntk = S * NKV * (HD / 2);
    rope_kernel<<<(ntq + 255) / 256, 256>>>(Qd, pos, S, NH);
    rope_kernel<<<(ntk + 255) / 256, 256>>>(Kd, pos, S, NKV);

    // Attention
    size_t smem = (size_t)(HD * QSTR + HD * KSTR + BKT * HD + BQ * BKT + BKT) * 4
                + (size_t)BKT * 4;
    cudaFuncSetAttribute(attn_kernel, cudaFuncAttributeMaxDynamicSharedMemorySize,
                         (int)smem);
    attn_kernel<<<dim3(S / BQ, NH), 512, smem>>>(Qd, Kd, Vd, amask, segs, Ad, S);

    // Output projection
    sgemm_kernel<<<dim3(H / GBN, S / GBM), 256>>>(Ad, Wo, out, S, H, H);
}

// round 3
// speedup vs baseline: 1.6525x; 1.6525x over previous
#include <cuda_runtime.h>
#include <cuda_bf16.h>
#include <math.h>
#include <stdint.h>

#define NH   16
#define NKV  4
#define HD   128
#define SMAX 2048
#define KDIM 2048

// ---------------- scratch (device globals; no allocation allowed) ----------
__device__ __align__(256) float g_Q[SMAX * NH * HD];
__device__ __align__(256) float g_K[SMAX * NKV * HD];
__device__ __align__(256) float g_V[SMAX * NKV * HD];
__device__ __align__(256) float g_A[SMAX * NH * HD];
__device__ __align__(256) __nv_bfloat16 g_Ahi[KDIM * KDIM];
__device__ __align__(256) __nv_bfloat16 g_Alo[KDIM * KDIM];
__device__ __align__(256) __nv_bfloat16 g_Bhi[KDIM * KDIM];
__device__ __align__(256) __nv_bfloat16 g_Blo[KDIM * KDIM];

// ---------------- helpers --------------------------------------------------
__device__ __forceinline__ uint32_t smem_u32(const void* p) {
    uint32_t a;
    asm("{ .reg .u64 t; cvta.to.shared.u64 t, %1; cvt.u32.u64 %0, t; }"
        : "=r"(a) : "l"(p));
    return a;
}

__device__ __forceinline__ void ldm_x4(uint32_t* r, uint32_t addr) {
    asm volatile("ldmatrix.sync.aligned.m8n8.x4.shared.b16 {%0,%1,%2,%3}, [%4];"
                 : "=r"(r[0]), "=r"(r[1]), "=r"(r[2]), "=r"(r[3]) : "r"(addr));
}
__device__ __forceinline__ void mma16816(float* d, const uint32_t* a,
                                         uint32_t b0, uint32_t b1) {
    asm volatile(
        "mma.sync.aligned.m16n8k16.row.col.f32.bf16.bf16.f32 "
        "{%0,%1,%2,%3}, {%4,%5,%6,%7}, {%8,%9}, {%0,%1,%2,%3};"
        : "+f"(d[0]), "+f"(d[1]), "+f"(d[2]), "+f"(d[3])
        : "r"(a[0]), "r"(a[1]), "r"(a[2]), "r"(a[3]), "r"(b0), "r"(b1));
}
__device__ __forceinline__ void cp_async16(uint32_t dst, const void* src) {
    asm volatile("cp.async.cg.shared.global [%0], [%1], 16;"
                 :: "r"(dst), "l"(src) : "memory");
}
#define CP_COMMIT() asm volatile("cp.async.commit_group;" ::: "memory")
#define CP_WAIT(n)  asm volatile("cp.async.wait_group %0;" :: "n"(n) : "memory")

// ---------------------------------------------------------------------------
// bf16 x3 split GEMM via mma.sync: C[2048, N] = A[2048,2048] @ Bt[N,2048]^T
// CTA tile 128x128, BK=64, 3-stage cp.async pipeline, 8 warps (2x4), SW128.
// ---------------------------------------------------------------------------
#define NC     (KDIM / 64)      // 32 K-chunks
#define STAGEB 65536            // Ahi|Alo|Bhi|Blo tiles, 16KB each
#define OFF_ALO 16384
#define OFF_BHI 32768
#define OFF_BLO 49152

__global__ __launch_bounds__(256, 1) void gemm_mma(
    const __nv_bfloat16* __restrict__ Ahi, const __nv_bfloat16* __restrict__ Alo,
    const __nv_bfloat16* __restrict__ Bhi, const __nv_bfloat16* __restrict__ Blo,
    float* __restrict__ C, int N)
{
    extern __shared__ char smem[];
    const uint32_t sb = smem_u32(smem);
    const int tid = threadIdx.x, lane = tid & 31, wid = tid >> 5;
    const int m0 = blockIdx.y * 128, n0 = blockIdx.x * 128;
    const int wm = (wid >> 2) * 64, wn = (wid & 3) * 32;

    auto load_half = [&](const __nv_bfloat16* src, int rowbase, uint32_t dstbase, int c) {
#pragma unroll
        for (int it = 0; it < 4; it++) {
            int idx = tid + it * 256;
            int row = idx >> 3, ch = idx & 7;
            const void* g = src + (size_t)(rowbase + row) * KDIM + c * 64 + ch * 8;
            uint32_t d = dstbase + row * 128 + ((ch ^ (row & 7)) << 4);
            cp_async16(d, g);
        }
    };
    auto load_chunk = [&](int c, int buf) {
        uint32_t base = sb + buf * STAGEB;
        load_half(Ahi, m0, base, c);
        load_half(Alo, m0, base + OFF_ALO, c);
        load_half(Bhi, n0, base + OFF_BHI, c);
        load_half(Blo, n0, base + OFF_BLO, c);
        CP_COMMIT();
    };

    // fragment address components (per-thread invariants)
    const int arow = wm + (lane & 15);              // + mt*16
    const int cA   = lane >> 4;                     // k-chunk bit
    const int brow = wn + ((lane >> 4) << 3) + (lane & 7);  // + np*16
    const int cB   = (lane >> 3) & 1;

    float d[4][4][4];
#pragma unroll
    for (int i = 0; i < 4; i++)
#pragma unroll
        for (int j = 0; j < 4; j++)
#pragma unroll
            for (int k = 0; k < 4; k++) d[i][j][k] = 0.f;

    load_chunk(0, 0);
    load_chunk(1, 1);

    for (int c = 0; c < NC; c++) {
        if (c < NC - 1) CP_WAIT(1); else CP_WAIT(0);
        __syncthreads();
        if (c + 2 < NC) load_chunk(c + 2, (c + 2) % 3);

        const uint32_t base = sb + (c % 3) * STAGEB;
#pragma unroll
        for (int ks = 0; ks < 4; ks++) {
            uint32_t ah[4][4], al[4][4], bh[2][4], bl[2][4];
#pragma unroll
            for (int mt = 0; mt < 4; mt++) {
                int row = arow + mt * 16;
                uint32_t addr = base + row * 128 + (((ks * 2 + cA) ^ (row & 7)) << 4);
                ldm_x4(ah[mt], addr);
                ldm_x4(al[mt], addr + OFF_ALO);
            }
#pragma unroll
            for (int np = 0; np < 2; np++) {
                int row = brow + np * 16;
                uint32_t addr = base + OFF_BHI + row * 128 +
                                (((ks * 2 + cB) ^ (row & 7)) << 4);
                ldm_x4(bh[np], addr);
                ldm_x4(bl[np], addr + (OFF_BLO - OFF_BHI));
            }
#pragma unroll
            for (int mt = 0; mt < 4; mt++)
#pragma unroll
                for (int np = 0; np < 2; np++)
#pragma unroll
                    for (int s = 0; s < 2; s++) {
                        int nt = np * 2 + s;
                        mma16816(d[mt][nt], ah[mt], bh[np][2 * s], bh[np][2 * s + 1]);
                        mma16816(d[mt][nt], ah[mt], bl[np][2 * s], bl[np][2 * s + 1]);
                        mma16816(d[mt][nt], al[mt], bh[np][2 * s], bh[np][2 * s + 1]);
                    }
        }
        __syncthreads();
    }

    // epilogue
#pragma unroll
    for (int mt = 0; mt < 4; mt++) {
        int r = m0 + wm + mt * 16 + (lane >> 2);
#pragma unroll
        for (int nt = 0; nt < 4; nt++) {
            int col = n0 + wn + nt * 8 + (lane & 3) * 2;
            *(float2*)(C + (size_t)r * N + col)       = make_float2(d[mt][nt][0], d[mt][nt][1]);
            *(float2*)(C + (size_t)(r + 8) * N + col) = make_float2(d[mt][nt][2], d[mt][nt][3]);
        }
    }
}

// ---------------------------------------------------------------------------
// fp32 -> bf16 hi/lo split (elementwise)
// ---------------------------------------------------------------------------
__global__ void cvt_split(const float* __restrict__ in,
                          __nv_bfloat16* __restrict__ hi,
                          __nv_bfloat16* __restrict__ lo, int n2)
{
    int i = blockIdx.x * blockDim.x + threadIdx.x;
    if (i >= n2) return;
    float2 v = ((const float2*)in)[i];
    __nv_bfloat16 hx = __float2bfloat16(v.x);
    __nv_bfloat16 hy = __float2bfloat16(v.y);
    __nv_bfloat162 h; h.x = hx; h.y = hy;
    __nv_bfloat162 l;
    l.x = __float2bfloat16(v.x - __bfloat162float(hx));
    l.y = __float2bfloat16(v.y - __bfloat162float(hy));
    ((__nv_bfloat162*)hi)[i] = h;
    ((__nv_bfloat162*)lo)[i] = l;
}

// ---------------------------------------------------------------------------
// W[K][N] fp32 -> Wt[N][K] bf16 hi/lo (tiled transpose + split)
// ---------------------------------------------------------------------------
__global__ void cvt_split_T(const float* __restrict__ W,
                            __nv_bfloat16* __restrict__ hi,
                            __nv_bfloat16* __restrict__ lo, int K, int N)
{
    __shared__ float t[32][33];
    int x = blockIdx.x * 32 + threadIdx.x;   // N index
    int y = blockIdx.y * 32 + threadIdx.y;   // K index
#pragma unroll
    for (int j = 0; j < 32; j += 8)
        t[threadIdx.y + j][threadIdx.x] = W[(size_t)(y + j) * N + x];
    __syncthreads();
    int x2 = blockIdx.y * 32 + threadIdx.x;  // K index (out col)
    int y2 = blockIdx.x * 32 + threadIdx.y;  // N index (out row)
#pragma unroll
    for (int j = 0; j < 32; j += 8) {
        float v = t[threadIdx.x][threadIdx.y + j];
        __nv_bfloat16 h = __float2bfloat16(v);
        hi[(size_t)(y2 + j) * K + x2] = h;
        lo[(size_t)(y2 + j) * K + x2] = __float2bfloat16(v - __bfloat162float(h));
    }
}

// ---------------------------------------------------------------------------
// RoPE in-place. X: [S][nh][128]; interleaved pairs (even, odd).
// ---------------------------------------------------------------------------
__global__ void rope_kernel(float* __restrict__ X, const int* __restrict__ pos,
                            int S, int nh)
{
    int idx = blockIdx.x * blockDim.x + threadIdx.x;
    int total = S * nh * (HD / 2);
    if (idx >= total) return;
    int i  = idx & 63;
    int sh = idx >> 6;
    int s  = sh / nh;
    float e = -(float)(2 * i) * (1.0f / 128.0f) * 13.287712379549449f;
    float freq = exp2f(e);
    float ang = (float)pos[s] * freq;
    float sn, cs;
    sincosf(ang, &sn, &cs);
    float2* p = (float2*)(X + (size_t)idx * 2);
    float2 v = *p;
    *p = make_float2(v.x * cs - v.y * sn, v.x * sn + v.y * cs);
}

// ---------------------------------------------------------------------------
// Flash attention (fp32), validated in round 0.
// ---------------------------------------------------------------------------
#define BQ   128
#define BKT  64
#define QSTR 132
#define KSTR 68

__global__ __launch_bounds__(512, 1) void attn_kernel(
    const float* __restrict__ Q, const float* __restrict__ K,
    const float* __restrict__ V,
    const int* __restrict__ amask, const int* __restrict__ segs,
    float* __restrict__ O, int S)
{
    extern __shared__ float sm[];
    float* Qst  = sm;
    float* Kst  = Qst + HD * QSTR;
    float* Vs   = Kst + HD * KSTR;
    float* Ps   = Vs + BKT * HD;
    float* kinv = Ps + BQ * BKT;
    int*   kseg = (int*)(kinv + BKT);

    const int tid = threadIdx.x;
    const int tx = tid & 15;
    const int ty = tid >> 4;
    const int h  = blockIdx.y;
    const int q0 = blockIdx.x * BQ;
    const int kvh = h >> 2;
    const float scale = 0.0883883476483184f;

#pragma unroll
    for (int it = 0; it < 8; it++) {
        int idx = tid + it * 512;
        int row = idx >> 5;
        int d4  = (idx & 31) * 4;
        float4 v = *(const float4*)(Q + ((size_t)(q0 + row) * NH + h) * HD + d4);
        Qst[(d4 + 0) * QSTR + row] = v.x * scale;
        Qst[(d4 + 1) * QSTR + row] = v.y * scale;
        Qst[(d4 + 2) * QSTR + row] = v.z * scale;
        Qst[(d4 + 3) * QSTR + row] = v.w * scale;
    }

    float m_i[4], l_i[4], acc[4][8];
#pragma unroll
    for (int i = 0; i < 4; i++) {
        m_i[i] = -1e30f; l_i[i] = 0.f;
#pragma unroll
        for (int j = 0; j < 8; j++) acc[i][j] = 0.f;
    }
    int qpos[4], qseg[4];
#pragma unroll
    for (int i = 0; i < 4; i++) {
        qpos[i] = q0 + ty * 4 + i;
        qseg[i] = segs[qpos[i]];
    }

    const int kend = q0 + BQ;
    for (int k0 = 0; k0 < kend; k0 += BKT) {
        __syncthreads();
#pragma unroll
        for (int it = 0; it < 4; it++) {
            int idx = tid + it * 512;
            int row = idx >> 5;
            int d4  = (idx & 31) * 4;
            float4 kv = *(const float4*)(K + ((size_t)(k0 + row) * NKV + kvh) * HD + d4);
            Kst[(d4 + 0) * KSTR + row] = kv.x;
            Kst[(d4 + 1) * KSTR + row] = kv.y;
            Kst[(d4 + 2) * KSTR + row] = kv.z;
            Kst[(d4 + 3) * KSTR + row] = kv.w;
            float4 vv = *(const float4*)(V + ((size_t)(k0 + row) * NKV + kvh) * HD + d4);
            *(float4*)(Vs + row * HD + d4) = vv;
        }
        if (tid < BKT) {
            kinv[tid] = (amask[k0 + tid] > 0) ? 0.f : 1.f;
            kseg[tid] = segs[k0 + tid];
        }
        __syncthreads();

        float s[4][4];
#pragma unroll
        for (int i = 0; i < 4; i++)
#pragma unroll
            for (int j = 0; j < 4; j++) s[i][j] = 0.f;

#pragma unroll 16
        for (int dd = 0; dd < HD; dd++) {
            float4 qv = *(const float4*)(Qst + dd * QSTR + ty * 4);
            float4 kv = *(const float4*)(Kst + dd * KSTR + tx * 4);
            float qa[4] = {qv.x, qv.y, qv.z, qv.w};
            float ka[4] = {kv.x, kv.y, kv.z, kv.w};
#pragma unroll
            for (int i = 0; i < 4; i++)
#pragma unroll
                for (int j = 0; j < 4; j++)
                    s[i][j] += qa[i] * ka[j];
        }

        float kin[4]; int ksg[4];
#pragma unroll
        for (int j = 0; j < 4; j++) {
            kin[j] = kinv[tx * 4 + j];
            ksg[j] = kseg[tx * 4 + j];
        }
#pragma unroll
        for (int i = 0; i < 4; i++)
#pragma unroll
            for (int j = 0; j < 4; j++) {
                int kp = k0 + tx * 4 + j;
                bool ok = (kp <= qpos[i]) && (kin[j] == 0.f) && (ksg[j] == qseg[i]);
                if (!ok) s[i][j] = -INFINITY;
            }

#pragma unroll
        for (int i = 0; i < 4; i++) {
            float mx = fmaxf(fmaxf(s[i][0], s[i][1]), fmaxf(s[i][2], s[i][3]));
#pragma unroll
            for (int o = 1; o < 16; o <<= 1)
                mx = fmaxf(mx, __shfl_xor_sync(0xffffffffu, mx, o));
            float mnew = fmaxf(m_i[i], mx);
            float alpha = __expf(m_i[i] - mnew);
            m_i[i] = mnew;
            float p0 = __expf(s[i][0] - mnew);
            float p1 = __expf(s[i][1] - mnew);
            float p2 = __expf(s[i][2] - mnew);
            float p3 = __expf(s[i][3] - mnew);
            *(float4*)(Ps + (ty * 4 + i) * BKT + tx * 4) = make_float4(p0, p1, p2, p3);
            float ps = p0 + p1 + p2 + p3;
#pragma unroll
            for (int o = 1; o < 16; o <<= 1)
                ps += __shfl_xor_sync(0xffffffffu, ps, o);
            l_i[i] = l_i[i] * alpha + ps;
#pragma unroll
            for (int j = 0; j < 8; j++) acc[i][j] *= alpha;
        }
        __syncthreads();

#pragma unroll 8
        for (int kk = 0; kk < BKT; kk++) {
            float4 v0 = *(const float4*)(Vs + kk * HD + tx * 8);
            float4 v1 = *(const float4*)(Vs + kk * HD + tx * 8 + 4);
            float vv[8] = {v0.x, v0.y, v0.z, v0.w, v1.x, v1.y, v1.z, v1.w};
#pragma unroll
            for (int i = 0; i < 4; i++) {
                float p = Ps[(ty * 4 + i) * BKT + kk];
#pragma unroll
                for (int j = 0; j < 8; j++)
                    acc[i][j] += p * vv[j];
            }
        }
    }

#pragma unroll
    for (int i = 0; i < 4; i++) {
        float inv = (l_i[i] > 0.f) ? (1.0f / l_i[i]) : 0.f;
        float* dst = O + ((size_t)qpos[i] * NH + h) * HD + tx * 8;
        *(float4*)(dst)     = make_float4(acc[i][0] * inv, acc[i][1] * inv,
                                          acc[i][2] * inv, acc[i][3] * inv);
        *(float4*)(dst + 4) = make_float4(acc[i][4] * inv, acc[i][5] * inv,
                                          acc[i][6] * inv, acc[i][7] * inv);
    }
}

// ---------------------------------------------------------------------------
// Host launcher
// ---------------------------------------------------------------------------
extern "C" void kernel_launch(void* const* d_in, const int* in_sizes, int n_in,
                              void* d_out, int out_size)
{
    const float* X     = (const float*)d_in[0];
    const int*   amask = (const int*)d_in[1];
    const int*   segs  = (const int*)d_in[2];
    const int*   pos   = (const int*)d_in[3];
    const float* Wq    = (const float*)d_in[4];
    const float* Wk    = (const float*)d_in[5];
    const float* Wv    = (const float*)d_in[6];
    const float* Wo    = (const float*)d_in[7];
    float* out = (float*)d_out;

    const int S   = in_sizes[3];
    const int H   = in_sizes[0] / S;        // 2048
    const int Hkv = in_sizes[5] / H;        // 512

    float *Qd, *Kd, *Vd, *Ad;
    __nv_bfloat16 *Ahi, *Alo, *Bhi, *Blo;
    cudaGetSymbolAddress((void**)&Qd, g_Q);
    cudaGetSymbolAddress((void**)&Kd, g_K);
    cudaGetSymbolAddress((void**)&Vd, g_V);
    cudaGetSymbolAddress((void**)&Ad, g_A);
    cudaGetSymbolAddress((void**)&Ahi, g_Ahi);
    cudaGetSymbolAddress((void**)&Alo, g_Alo);
    cudaGetSymbolAddress((void**)&Bhi, g_Bhi);
    cudaGetSymbolAddress((void**)&Blo, g_Blo);

    const int gemm_smem = 3 * STAGEB;   // 192KB
    cudaFuncSetAttribute(gemm_mma, cudaFuncAttributeMaxDynamicSharedMemorySize,
                         gemm_smem);

    const int n2 = (S * H) / 2;
    // split X
    cvt_split<<<(n2 + 255) / 256, 256>>>(X, Ahi, Alo, n2);

    // Q = X @ Wq
    cvt_split_T<<<dim3(H / 32, H / 32), dim3(32, 8)>>>(Wq, Bhi, Blo, H, H);
    gemm_mma<<<dim3(H / 128, S / 128), 256, gemm_smem>>>(Ahi, Alo, Bhi, Blo, Qd, H);
    // K = X @ Wk
    cvt_split_T<<<dim3(Hkv / 32, H / 32), dim3(32, 8)>>>(Wk, Bhi, Blo, H, Hkv);
    gemm_mma<<<dim3(Hkv / 128, S / 128), 256, gemm_smem>>>(Ahi, Alo, Bhi, Blo, Kd, Hkv);
    // V = X @ Wv
    cvt_split_T<<<dim3(Hkv / 32, H / 32), dim3(32, 8)>>>(Wv, Bhi, Blo, H, Hkv);
    gemm_mma<<<dim3(Hkv / 128, S / 128), 256, gemm_smem>>>(Ahi, Alo, Bhi, Blo, Vd, Hkv);

    // RoPE
    int ntq = S * NH  * (HD / 2);
    int ntk = S * NKV * (HD / 2);
    rope_kernel<<<(ntq + 255) / 256, 256>>>(Qd, pos, S, NH);
    rope_kernel<<<(ntk + 255) / 256, 256>>>(Kd, pos, S, NKV);

    // Attention
    size_t smem = (size_t)(HD * QSTR + HD * KSTR + BKT * HD + BQ * BKT + BKT) * 4
                + (size_t)BKT * 4;
    cudaFuncSetAttribute(attn_kernel, cudaFuncAttributeMaxDynamicSharedMemorySize,
                         (int)smem);
    attn_kernel<<<dim3(S / BQ, NH), 512, smem>>>(Qd, Kd, Vd, amask, segs, Ad, S);

    // out = A @ Wo
    cvt_split<<<(n2 + 255) / 256, 256>>>(Ad, Ahi, Alo, n2);
    cvt_split_T<<<dim3(H / 32, H / 32), dim3(32, 8)>>>(Wo, Bhi, Blo, H, H);
    gemm_mma<<<dim3(H / 128, S / 128), 256, gemm_smem>>>(Ahi, Alo, Bhi, Blo, out, H);
}

// round 5
// speedup vs baseline: 3.9409x; 2.3847x over previous
#include <cuda_runtime.h>
#include <cuda_bf16.h>
#include <cuda_fp16.h>
#include <math.h>
#include <stdint.h>

#define NH   16
#define NKV  4
#define HD   128
#define SMAX 2048
#define KDIM 2048

// ---------------- scratch (device globals; no allocation allowed) ----------
__device__ __align__(256) float g_Q[SMAX * NH * HD];
__device__ __align__(256) float g_K[SMAX * NKV * HD];
__device__ __align__(256) float g_V[SMAX * NKV * HD];
__device__ __align__(256) float g_A[SMAX * NH * HD];
__device__ __align__(256) __nv_bfloat16 g_Ahi[KDIM * KDIM];
__device__ __align__(256) __nv_bfloat16 g_Alo[KDIM * KDIM];
__device__ __align__(256) __nv_bfloat16 g_Bhi[KDIM * KDIM];
__device__ __align__(256) __nv_bfloat16 g_Blo[KDIM * KDIM];
__device__ __align__(256) __half h_Q[SMAX * NH * HD];
__device__ __align__(256) __half h_K[SMAX * NKV * HD];
__device__ __align__(256) __half h_V[SMAX * NKV * HD];

// ---------------- helpers --------------------------------------------------
__device__ __forceinline__ uint32_t smem_u32(const void* p) {
    uint32_t a;
    asm("{ .reg .u64 t; cvta.to.shared.u64 t, %1; cvt.u32.u64 %0, t; }"
        : "=r"(a) : "l"(p));
    return a;
}
__device__ __forceinline__ uint32_t h2_as_u32(__half2 h) {
    return *reinterpret_cast<uint32_t*>(&h);
}
__device__ __forceinline__ void ldm_x4(uint32_t* r, uint32_t addr) {
    asm volatile("ldmatrix.sync.aligned.m8n8.x4.shared.b16 {%0,%1,%2,%3}, [%4];"
                 : "=r"(r[0]), "=r"(r[1]), "=r"(r[2]), "=r"(r[3]) : "r"(addr));
}
__device__ __forceinline__ void ldm_x4_t(uint32_t* r, uint32_t addr) {
    asm volatile("ldmatrix.sync.aligned.m8n8.x4.trans.shared.b16 {%0,%1,%2,%3}, [%4];"
                 : "=r"(r[0]), "=r"(r[1]), "=r"(r[2]), "=r"(r[3]) : "r"(addr));
}
__device__ __forceinline__ void mma_bf16(float* d, const uint32_t* a,
                                         uint32_t b0, uint32_t b1) {
    asm volatile(
        "mma.sync.aligned.m16n8k16.row.col.f32.bf16.bf16.f32 "
        "{%0,%1,%2,%3}, {%4,%5,%6,%7}, {%8,%9}, {%0,%1,%2,%3};"
        : "+f"(d[0]), "+f"(d[1]), "+f"(d[2]), "+f"(d[3])
        : "r"(a[0]), "r"(a[1]), "r"(a[2]), "r"(a[3]), "r"(b0), "r"(b1));
}
__device__ __forceinline__ void mma_f16(float* d, const uint32_t* a,
                                        uint32_t b0, uint32_t b1) {
    asm volatile(
        "mma.sync.aligned.m16n8k16.row.col.f32.f16.f16.f32 "
        "{%0,%1,%2,%3}, {%4,%5,%6,%7}, {%8,%9}, {%0,%1,%2,%3};"
        : "+f"(d[0]), "+f"(d[1]), "+f"(d[2]), "+f"(d[3])
        : "r"(a[0]), "r"(a[1]), "r"(a[2]), "r"(a[3]), "r"(b0), "r"(b1));
}
__device__ __forceinline__ void cp_async16(uint32_t dst, const void* src) {
    asm volatile("cp.async.cg.shared.global [%0], [%1], 16;"
                 :: "r"(dst), "l"(src) : "memory");
}
#define CP_COMMIT() asm volatile("cp.async.commit_group;" ::: "memory")
#define CP_WAIT0()  asm volatile("cp.async.wait_group 0;" ::: "memory")
#define CP_WAIT1()  asm volatile("cp.async.wait_group 1;" ::: "memory")

// ---------------------------------------------------------------------------
// bf16 x3 split GEMM via mma.sync: C[2048, N] = A[2048,2048] @ Bt[N,2048]^T
// CTA 128x128, BK=64, 3-stage cp.async pipeline, 16 warps (4x4, 32x32 each).
// ---------------------------------------------------------------------------
#define NC      (KDIM / 64)
#define STAGEB  65536
#define OFF_ALO 16384
#define OFF_BHI 32768
#define OFF_BLO 49152

__global__ __launch_bounds__(512, 1) void gemm_mma(
    const __nv_bfloat16* __restrict__ Ahi, const __nv_bfloat16* __restrict__ Alo,
    const __nv_bfloat16* __restrict__ Bhi, const __nv_bfloat16* __restrict__ Blo,
    float* __restrict__ C, int N)
{
    extern __shared__ char smem[];
    const uint32_t sb = smem_u32(smem);
    const int tid = threadIdx.x, lane = tid & 31, wid = tid >> 5;
    const int m0 = blockIdx.y * 128, n0 = blockIdx.x * 128;
    const int wm = (wid >> 2) * 32, wn = (wid & 3) * 32;

    auto load_half_t = [&](const __nv_bfloat16* src, int rowbase, uint32_t dstbase, int c) {
#pragma unroll
        for (int it = 0; it < 2; it++) {
            int idx = tid + it * 512;
            int row = idx >> 3, ch = idx & 7;
            const void* g = src + (size_t)(rowbase + row) * KDIM + c * 64 + ch * 8;
            uint32_t d = dstbase + row * 128 + ((ch ^ (row & 7)) << 4);
            cp_async16(d, g);
        }
    };
    auto load_chunk = [&](int c, int buf) {
        uint32_t base = sb + buf * STAGEB;
        load_half_t(Ahi, m0, base, c);
        load_half_t(Alo, m0, base + OFF_ALO, c);
        load_half_t(Bhi, n0, base + OFF_BHI, c);
        load_half_t(Blo, n0, base + OFF_BLO, c);
        CP_COMMIT();
    };

    const int arow = wm + (lane & 15);
    const int cA   = lane >> 4;
    const int brow = wn + ((lane >> 4) << 3) + (lane & 7);
    const int cB   = (lane >> 3) & 1;

    float d[2][4][4];
#pragma unroll
    for (int i = 0; i < 2; i++)
#pragma unroll
        for (int j = 0; j < 4; j++)
#pragma unroll
            for (int k = 0; k < 4; k++) d[i][j][k] = 0.f;

    load_chunk(0, 0);
    load_chunk(1, 1);

    for (int c = 0; c < NC; c++) {
        if (c < NC - 1) CP_WAIT1(); else CP_WAIT0();
        __syncthreads();
        if (c + 2 < NC) load_chunk(c + 2, (c + 2) % 3);

        const uint32_t base = sb + (c % 3) * STAGEB;
#pragma unroll
        for (int ks = 0; ks < 4; ks++) {
            uint32_t ah[2][4], al[2][4], bh[2][4], bl[2][4];
#pragma unroll
            for (int mt = 0; mt < 2; mt++) {
                int row = arow + mt * 16;
                uint32_t addr = base + row * 128 + (((ks * 2 + cA) ^ (row & 7)) << 4);
                ldm_x4(ah[mt], addr);
                ldm_x4(al[mt], addr + OFF_ALO);
            }
#pragma unroll
            for (int np = 0; np < 2; np++) {
                int row = brow + np * 16;
                uint32_t addr = base + OFF_BHI + row * 128 +
                                (((ks * 2 + cB) ^ (row & 7)) << 4);
                ldm_x4(bh[np], addr);
                ldm_x4(bl[np], addr + (OFF_BLO - OFF_BHI));
            }
#pragma unroll
            for (int mt = 0; mt < 2; mt++)
#pragma unroll
                for (int np = 0; np < 2; np++)
#pragma unroll
                    for (int s = 0; s < 2; s++) {
                        int nt = np * 2 + s;
                        mma_bf16(d[mt][nt], ah[mt], bh[np][2 * s], bh[np][2 * s + 1]);
                        mma_bf16(d[mt][nt], ah[mt], bl[np][2 * s], bl[np][2 * s + 1]);
                        mma_bf16(d[mt][nt], al[mt], bh[np][2 * s], bh[np][2 * s + 1]);
                    }
        }
        __syncthreads();
    }

#pragma unroll
    for (int mt = 0; mt < 2; mt++) {
        int r = m0 + wm + mt * 16 + (lane >> 2);
#pragma unroll
        for (int nt = 0; nt < 4; nt++) {
            int col = n0 + wn + nt * 8 + (lane & 3) * 2;
            *(float2*)(C + (size_t)r * N + col)       = make_float2(d[mt][nt][0], d[mt][nt][1]);
            *(float2*)(C + (size_t)(r + 8) * N + col) = make_float2(d[mt][nt][2], d[mt][nt][3]);
        }
    }
}

// ---------------------------------------------------------------------------
// conversions
// ---------------------------------------------------------------------------
__global__ void cvt_split(const float* __restrict__ in,
                          __nv_bfloat16* __restrict__ hi,
                          __nv_bfloat16* __restrict__ lo, int n2)
{
    int i = blockIdx.x * blockDim.x + threadIdx.x;
    if (i >= n2) return;
    float2 v = ((const float2*)in)[i];
    __nv_bfloat16 hx = __float2bfloat16(v.x);
    __nv_bfloat16 hy = __float2bfloat16(v.y);
    __nv_bfloat162 h; h.x = hx; h.y = hy;
    __nv_bfloat162 l;
    l.x = __float2bfloat16(v.x - __bfloat162float(hx));
    l.y = __float2bfloat16(v.y - __bfloat162float(hy));
    ((__nv_bfloat162*)hi)[i] = h;
    ((__nv_bfloat162*)lo)[i] = l;
}

__global__ void cvt_split_T(const float* __restrict__ W,
                            __nv_bfloat16* __restrict__ hi,
                            __nv_bfloat16* __restrict__ lo, int K, int N)
{
    __shared__ float t[32][33];
    int x = blockIdx.x * 32 + threadIdx.x;
    int y = blockIdx.y * 32 + threadIdx.y;
#pragma unroll
    for (int j = 0; j < 32; j += 8)
        t[threadIdx.y + j][threadIdx.x] = W[(size_t)(y + j) * N + x];
    __syncthreads();
    int x2 = blockIdx.y * 32 + threadIdx.x;
    int y2 = blockIdx.x * 32 + threadIdx.y;
#pragma unroll
    for (int j = 0; j < 32; j += 8) {
        float v = t[threadIdx.x][threadIdx.y + j];
        __nv_bfloat16 h = __float2bfloat16(v);
        hi[(size_t)(y2 + j) * K + x2] = h;
        lo[(size_t)(y2 + j) * K + x2] = __float2bfloat16(v - __bfloat162float(h));
    }
}

// RoPE fp32 -> fp16 (optionally pre-scaled); X layout [S][nh][128]
__global__ void rope_half(const float* __restrict__ X, __half* __restrict__ Y,
                          const int* __restrict__ pos, int S, int nh, float oscale)
{
    int idx = blockIdx.x * blockDim.x + threadIdx.x;
    int total = S * nh * (HD / 2);
    if (idx >= total) return;
    int i  = idx & 63;
    int sh = idx >> 6;
    int s  = sh / nh;
    float e = -(float)(2 * i) * (1.0f / 128.0f) * 13.287712379549449f;
    float freq = exp2f(e);
    float ang = (float)pos[s] * freq;
    float sn, cs;
    sincosf(ang, &sn, &cs);
    float2 v = ((const float2*)X)[idx];
    float o0 = (v.x * cs - v.y * sn) * oscale;
    float o1 = (v.x * sn + v.y * cs) * oscale;
    ((__half2*)Y)[idx] = __floats2half2_rn(o0, o1);
}

__global__ void cvt_half(const float* __restrict__ in, __half* __restrict__ out, int n2)
{
    int i = blockIdx.x * blockDim.x + threadIdx.x;
    if (i >= n2) return;
    float2 v = ((const float2*)in)[i];
    ((__half2*)out)[i] = __floats2half2_rn(v.x, v.y);
}

// ---------------------------------------------------------------------------
// fp16 mma.sync flash attention.
// CTA: 128 threads (4 warps), BQ=64 q rows (warp=16), kv tiles of 64.
// K/V double-buffered cp.async; Q fragments register-resident.
// ---------------------------------------------------------------------------
#define ATSTR 272           // 136 halves per row
#define AT_K  17408
#define AT_V  52224
#define AT_MC 87040
#define AT_SMEM 87552

__global__ __launch_bounds__(128, 2) void attn_mma(
    const __half* __restrict__ Qh, const __half* __restrict__ Kh,
    const __half* __restrict__ Vh,
    const int* __restrict__ amask, const int* __restrict__ segs,
    float* __restrict__ O, int S)
{
    extern __shared__ char sm[];
    const uint32_t sb = smem_u32(sm);
    const int tid = threadIdx.x, lane = tid & 31, wid = tid >> 5;
    const int h = blockIdx.y;
    const int qb = (int)gridDim.x - 1 - (int)blockIdx.x;   // long blocks first
    const int q0 = qb * 64;
    const int kvh = h >> 2;
    const int ntile = qb + 1;

    auto prefetch = [&](int t) {
        int k0 = t * 64;
        int buf = t & 1;
#pragma unroll
        for (int it = 0; it < 8; it++) {
            int idx = tid + it * 128;
            int row = idx >> 4, ch = idx & 15;
            cp_async16(sb + AT_K + buf * (64 * ATSTR) + row * ATSTR + ch * 16,
                       Kh + ((size_t)(k0 + row) * NKV + kvh) * HD + ch * 8);
            cp_async16(sb + AT_V + buf * (64 * ATSTR) + row * ATSTR + ch * 16,
                       Vh + ((size_t)(k0 + row) * NKV + kvh) * HD + ch * 8);
        }
        if (tid < 64) {
            int a = amask[k0 + tid];
            ((int*)(sm + AT_MC))[buf * 64 + tid] =
                (a > 0) ? segs[k0 + tid] : 0x7fffffff;
        }
        CP_COMMIT();
    };

    // prologue: Q tile + tile 0
#pragma unroll
    for (int it = 0; it < 8; it++) {
        int idx = tid + it * 128;
        int row = idx >> 4, ch = idx & 15;
        cp_async16(sb + row * ATSTR + ch * 16,
                   Qh + ((size_t)(q0 + row) * NH + h) * HD + ch * 8);
    }
    prefetch(0);

    const int qr0 = q0 + wid * 16 + (lane >> 2);
    const int qr1 = qr0 + 8;
    const int qseg0 = segs[qr0];
    const int qseg1 = segs[qr1];
    const int colb = (lane & 3) * 2;

    float o[16][4];
#pragma unroll
    for (int j = 0; j < 16; j++)
#pragma unroll
        for (int k = 0; k < 4; k++) o[j][k] = 0.f;
    float m0 = -1e30f, m1 = -1e30f, l0 = 0.f, l1 = 0.f;
    uint32_t qf[8][4];

    for (int t = 0; t < ntile; t++) {
        const int k0 = t * 64;
        const int buf = t & 1;
        if (t + 1 < ntile) { prefetch(t + 1); CP_WAIT1(); }
        else               { CP_WAIT0(); }
        __syncthreads();

        if (t == 0) {
#pragma unroll
            for (int ks = 0; ks < 8; ks++) {
                uint32_t addr = sb + (wid * 16 + (lane & 15)) * ATSTR +
                                (ks * 16 + (lane >> 4) * 8) * 2;
                ldm_x4(qf[ks], addr);
            }
        }

        // ---- S = Q K^T ----
        float sf[8][4];
#pragma unroll
        for (int j = 0; j < 8; j++)
#pragma unroll
            for (int k = 0; k < 4; k++) sf[j][k] = 0.f;

        const uint32_t kb = sb + AT_K + buf * (64 * ATSTR);
#pragma unroll
        for (int ks = 0; ks < 8; ks++) {
            uint32_t bk[4][4];
#pragma unroll
            for (int np = 0; np < 4; np++) {
                uint32_t addr = kb + (np * 16 + ((lane >> 4) << 3) + (lane & 7)) * ATSTR +
                                (ks * 16 + ((lane >> 3) & 1) * 8) * 2;
                ldm_x4(bk[np], addr);
            }
#pragma unroll
            for (int np = 0; np < 4; np++)
#pragma unroll
                for (int s = 0; s < 2; s++)
                    mma_f16(sf[np * 2 + s], qf[ks], bk[np][2 * s], bk[np][2 * s + 1]);
        }

        // ---- mask ----
        const int* kc = (const int*)(sm + AT_MC) + buf * 64;
#pragma unroll
        for (int j = 0; j < 8; j++) {
            int c0 = j * 8 + colb, c1 = c0 + 1;
            int kp0 = k0 + c0, kp1 = k0 + c1;
            int kc0 = kc[c0], kc1 = kc[c1];
            if (!(kp0 <= qr0 && kc0 == qseg0)) sf[j][0] = -1e30f;
            if (!(kp1 <= qr0 && kc1 == qseg0)) sf[j][1] = -1e30f;
            if (!(kp0 <= qr1 && kc0 == qseg1)) sf[j][2] = -1e30f;
            if (!(kp1 <= qr1 && kc1 == qseg1)) sf[j][3] = -1e30f;
        }

        // ---- online softmax ----
        float mx0 = -1e30f, mx1 = -1e30f;
#pragma unroll
        for (int j = 0; j < 8; j++) {
            mx0 = fmaxf(mx0, fmaxf(sf[j][0], sf[j][1]));
            mx1 = fmaxf(mx1, fmaxf(sf[j][2], sf[j][3]));
        }
        mx0 = fmaxf(mx0, __shfl_xor_sync(0xffffffffu, mx0, 1));
        mx0 = fmaxf(mx0, __shfl_xor_sync(0xffffffffu, mx0, 2));
        mx1 = fmaxf(mx1, __shfl_xor_sync(0xffffffffu, mx1, 1));
        mx1 = fmaxf(mx1, __shfl_xor_sync(0xffffffffu, mx1, 2));
        float mn0 = fmaxf(m0, mx0), mn1 = fmaxf(m1, mx1);
        float a0 = __expf(m0 - mn0), a1 = __expf(m1 - mn1);
        m0 = mn0; m1 = mn1;
        float s0 = 0.f, s1 = 0.f;
#pragma unroll
        for (int j = 0; j < 8; j++) {
            sf[j][0] = __expf(sf[j][0] - mn0);
            sf[j][1] = __expf(sf[j][1] - mn0);
            sf[j][2] = __expf(sf[j][2] - mn1);
            sf[j][3] = __expf(sf[j][3] - mn1);
            s0 += sf[j][0] + sf[j][1];
            s1 += sf[j][2] + sf[j][3];
        }
        s0 += __shfl_xor_sync(0xffffffffu, s0, 1);
        s0 += __shfl_xor_sync(0xffffffffu, s0, 2);
        s1 += __shfl_xor_sync(0xffffffffu, s1, 1);
        s1 += __shfl_xor_sync(0xffffffffu, s1, 2);
        l0 = l0 * a0 + s0;
        l1 = l1 * a1 + s1;
#pragma unroll
        for (int j = 0; j < 16; j++) {
            o[j][0] *= a0; o[j][1] *= a0;
            o[j][2] *= a1; o[j][3] *= a1;
        }

        // ---- P fragments (fp16) ----
        uint32_t pa[4][4];
#pragma unroll
        for (int kk = 0; kk < 4; kk++) {
            pa[kk][0] = h2_as_u32(__floats2half2_rn(sf[2 * kk][0], sf[2 * kk][1]));
            pa[kk][1] = h2_as_u32(__floats2half2_rn(sf[2 * kk][2], sf[2 * kk][3]));
            pa[kk][2] = h2_as_u32(__floats2half2_rn(sf[2 * kk + 1][0], sf[2 * kk + 1][1]));
            pa[kk][3] = h2_as_u32(__floats2half2_rn(sf[2 * kk + 1][2], sf[2 * kk + 1][3]));
        }

        // ---- O += P V ----
        const uint32_t vb = sb + AT_V + buf * (64 * ATSTR);
#pragma unroll
        for (int ks = 0; ks < 4; ks++) {
            uint32_t bv[8][4];
#pragma unroll
            for (int nb = 0; nb < 8; nb++) {
                uint32_t addr = vb + (ks * 16 + (lane & 15)) * ATSTR +
                                (nb * 16 + (lane >> 4) * 8) * 2;
                ldm_x4_t(bv[nb], addr);
            }
#pragma unroll
            for (int nb = 0; nb < 8; nb++)
#pragma unroll
                for (int s = 0; s < 2; s++)
                    mma_f16(o[nb * 2 + s], pa[ks], bv[nb][2 * s], bv[nb][2 * s + 1]);
        }
        __syncthreads();
    }

    float inv0 = (l0 > 0.f) ? 1.f / l0 : 0.f;
    float inv1 = (l1 > 0.f) ? 1.f / l1 : 0.f;
#pragma unroll
    for (int j = 0; j < 16; j++) {
        int col = h * HD + j * 8 + colb;
        *(float2*)(O + (size_t)qr0 * (NH * HD) + col) = make_float2(o[j][0] * inv0, o[j][1] * inv0);
        *(float2*)(O + (size_t)qr1 * (NH * HD) + col) = make_float2(o[j][2] * inv1, o[j][3] * inv1);
    }
}

// ---------------------------------------------------------------------------
// Host launcher
// ---------------------------------------------------------------------------
extern "C" void kernel_launch(void* const* d_in, const int* in_sizes, int n_in,
                              void* d_out, int out_size)
{
    const float* X     = (const float*)d_in[0];
    const int*   amask = (const int*)d_in[1];
    const int*   segs  = (const int*)d_in[2];
    const int*   pos   = (const int*)d_in[3];
    const float* Wq    = (const float*)d_in[4];
    const float* Wk    = (const float*)d_in[5];
    const float* Wv    = (const float*)d_in[6];
    const float* Wo    = (const float*)d_in[7];
    float* out = (float*)d_out;

    const int S   = in_sizes[3];
    const int H   = in_sizes[0] / S;        // 2048
    const int Hkv = in_sizes[5] / H;        // 512

    float *Qd, *Kd, *Vd, *Ad;
    __nv_bfloat16 *Ahi, *Alo, *Bhi, *Blo;
    __half *Qh, *Kh, *Vh;
    cudaGetSymbolAddress((void**)&Qd, g_Q);
    cudaGetSymbolAddress((void**)&Kd, g_K);
    cudaGetSymbolAddress((void**)&Vd, g_V);
    cudaGetSymbolAddress((void**)&Ad, g_A);
    cudaGetSymbolAddress((void**)&Ahi, g_Ahi);
    cudaGetSymbolAddress((void**)&Alo, g_Alo);
    cudaGetSymbolAddress((void**)&Bhi, g_Bhi);
    cudaGetSymbolAddress((void**)&Blo, g_Blo);
    cudaGetSymbolAddress((void**)&Qh, h_Q);
    cudaGetSymbolAddress((void**)&Kh, h_K);
    cudaGetSymbolAddress((void**)&Vh, h_V);

    const int gemm_smem = 3 * STAGEB;   // 192KB
    cudaFuncSetAttribute(gemm_mma, cudaFuncAttributeMaxDynamicSharedMemorySize,
                         gemm_smem);
    cudaFuncSetAttribute(attn_mma, cudaFuncAttributeMaxDynamicSharedMemorySize,
                         AT_SMEM);

    const int n2 = (S * H) / 2;
    cvt_split<<<(n2 + 255) / 256, 256>>>(X, Ahi, Alo, n2);

    cvt_split_T<<<dim3(H / 32, H / 32), dim3(32, 8)>>>(Wq, Bhi, Blo, H, H);
    gemm_mma<<<dim3(H / 128, S / 128), 512, gemm_smem>>>(Ahi, Alo, Bhi, Blo, Qd, H);
    cvt_split_T<<<dim3(Hkv / 32, H / 32), dim3(32, 8)>>>(Wk, Bhi, Blo, H, Hkv);
    gemm_mma<<<dim3(Hkv / 128, S / 128), 512, gemm_smem>>>(Ahi, Alo, Bhi, Blo, Kd, Hkv);
    cvt_split_T<<<dim3(Hkv / 32, H / 32), dim3(32, 8)>>>(Wv, Bhi, Blo, H, Hkv);
    gemm_mma<<<dim3(Hkv / 128, S / 128), 512, gemm_smem>>>(Ahi, Alo, Bhi, Blo, Vd, Hkv);

    // RoPE + fp16 conversion (Q pre-scaled by 1/sqrt(hd))
    const float scale = 0.0883883476483184f;
    int ntq = S * NH  * (HD / 2);
    int ntk = S * NKV * (HD / 2);
    rope_half<<<(ntq + 255) / 256, 256>>>(Qd, Qh, pos, S, NH, scale);
    rope_half<<<(ntk + 255) / 256, 256>>>(Kd, Kh, pos, S, NKV, 1.0f);
    cvt_half<<<((S * NKV * HD / 2) + 255) / 256, 256>>>(Vd, Vh, S * NKV * HD / 2);

    // fp16 tensor-core flash attention
    attn_mma<<<dim3(S / 64, NH), 128, AT_SMEM>>>(Qh, Kh, Vh, amask, segs, Ad, S);

    // out = A @ Wo
    cvt_split<<<(n2 + 255) / 256, 256>>>(Ad, Ahi, Alo, n2);
    cvt_split_T<<<dim3(H / 32, H / 32), dim3(32, 8)>>>(Wo, Bhi, Blo, H, H);
    gemm_mma<<<dim3(H / 128, S / 128), 512, gemm_smem>>>(Ahi, Alo, Bhi, Blo, out, H);
}

// round 6
// speedup vs baseline: 4.5982x; 1.1668x over previous
#include <cuda_runtime.h>
#include <cuda_bf16.h>
#include <cuda_fp16.h>
#include <math.h>
#include <stdint.h>

#define NH   16
#define NKV  4
#define HD   128
#define SMAX 2048
#define KDIM 2048

// ---------------- scratch (device globals; no allocation allowed) ----------
__device__ __align__(256) __nv_bfloat16 g_Ahi[SMAX * KDIM];
__device__ __align__(256) __nv_bfloat16 g_Alo[SMAX * KDIM];
__device__ __align__(256) __nv_bfloat16 g_Bhi[3072 * KDIM];
__device__ __align__(256) __nv_bfloat16 g_Blo[3072 * KDIM];
__device__ __align__(256) __half h_Q[SMAX * NH * HD];
__device__ __align__(256) __half h_K[SMAX * NKV * HD];
__device__ __align__(256) __half h_V[SMAX * NKV * HD];
__device__ __align__(256) float2 g_rope[SMAX * 64];

// ---------------- helpers --------------------------------------------------
__device__ __forceinline__ uint32_t smem_u32(const void* p) {
    uint32_t a;
    asm("{ .reg .u64 t; cvta.to.shared.u64 t, %1; cvt.u32.u64 %0, t; }"
        : "=r"(a) : "l"(p));
    return a;
}
__device__ __forceinline__ uint32_t h2_as_u32(__half2 h) {
    return *reinterpret_cast<uint32_t*>(&h);
}
__device__ __forceinline__ void ldm_x4(uint32_t* r, uint32_t addr) {
    asm volatile("ldmatrix.sync.aligned.m8n8.x4.shared.b16 {%0,%1,%2,%3}, [%4];"
                 : "=r"(r[0]), "=r"(r[1]), "=r"(r[2]), "=r"(r[3]) : "r"(addr));
}
__device__ __forceinline__ void ldm_x4_t(uint32_t* r, uint32_t addr) {
    asm volatile("ldmatrix.sync.aligned.m8n8.x4.trans.shared.b16 {%0,%1,%2,%3}, [%4];"
                 : "=r"(r[0]), "=r"(r[1]), "=r"(r[2]), "=r"(r[3]) : "r"(addr));
}
__device__ __forceinline__ void mma_bf16(float* d, const uint32_t* a,
                                         uint32_t b0, uint32_t b1) {
    asm volatile(
        "mma.sync.aligned.m16n8k16.row.col.f32.bf16.bf16.f32 "
        "{%0,%1,%2,%3}, {%4,%5,%6,%7}, {%8,%9}, {%0,%1,%2,%3};"
        : "+f"(d[0]), "+f"(d[1]), "+f"(d[2]), "+f"(d[3])
        : "r"(a[0]), "r"(a[1]), "r"(a[2]), "r"(a[3]), "r"(b0), "r"(b1));
}
__device__ __forceinline__ void mma_f16(float* d, const uint32_t* a,
                                        uint32_t b0, uint32_t b1) {
    asm volatile(
        "mma.sync.aligned.m16n8k16.row.col.f32.f16.f16.f32 "
        "{%0,%1,%2,%3}, {%4,%5,%6,%7}, {%8,%9}, {%0,%1,%2,%3};"
        : "+f"(d[0]), "+f"(d[1]), "+f"(d[2]), "+f"(d[3])
        : "r"(a[0]), "r"(a[1]), "r"(a[2]), "r"(a[3]), "r"(b0), "r"(b1));
}
__device__ __forceinline__ void cp_async16(uint32_t dst, const void* src) {
    asm volatile("cp.async.cg.shared.global [%0], [%1], 16;"
                 :: "r"(dst), "l"(src) : "memory");
}
#define CP_COMMIT() asm volatile("cp.async.commit_group;" ::: "memory")
#define CP_WAIT0()  asm volatile("cp.async.wait_group 0;" ::: "memory")
#define CP_WAIT1()  asm volatile("cp.async.wait_group 1;" ::: "memory")

// ---------------------------------------------------------------------------
// bf16 x3 split GEMM via mma.sync. A = g_Ahi/g_Alo [2048][2048],
// B = g_Bhi/g_Blo [N][2048] (pre-transposed). CTA 128x128, BK=64,
// 3-stage cp.async pipeline, 16 warps (4x4 of 32x32).
// qkv=0: C fp32 [2048][N].  qkv=1: fused epilogue (rope+fp16) into h_Q/h_K/h_V.
// ---------------------------------------------------------------------------
#define NC      (KDIM / 64)
#define STAGEB  65536
#define OFF_ALO 16384
#define OFF_BHI 32768
#define OFF_BLO 49152

__global__ __launch_bounds__(512, 1) void gemm_mma(float* __restrict__ C,
                                                   int N, int qkv)
{
    extern __shared__ char smem[];
    const uint32_t sb = smem_u32(smem);
    const int tid = threadIdx.x, lane = tid & 31, wid = tid >> 5;
    const int m0 = blockIdx.y * 128, n0 = blockIdx.x * 128;
    const int wm = (wid >> 2) * 32, wn = (wid & 3) * 32;

    auto load_half_t = [&](const __nv_bfloat16* src, int rowbase, uint32_t dstbase, int c) {
#pragma unroll
        for (int it = 0; it < 2; it++) {
            int idx = tid + it * 512;
            int row = idx >> 3, ch = idx & 7;
            const void* g = src + (size_t)(rowbase + row) * KDIM + c * 64 + ch * 8;
            uint32_t dst = dstbase + row * 128 + ((ch ^ (row & 7)) << 4);
            cp_async16(dst, g);
        }
    };
    auto load_chunk = [&](int c, int buf) {
        uint32_t base = sb + buf * STAGEB;
        load_half_t(g_Ahi, m0, base, c);
        load_half_t(g_Alo, m0, base + OFF_ALO, c);
        load_half_t(g_Bhi, n0, base + OFF_BHI, c);
        load_half_t(g_Blo, n0, base + OFF_BLO, c);
        CP_COMMIT();
    };

    const int arow = wm + (lane & 15);
    const int cA   = lane >> 4;
    const int brow = wn + ((lane >> 4) << 3) + (lane & 7);
    const int cB   = (lane >> 3) & 1;

    float d[2][4][4];
#pragma unroll
    for (int i = 0; i < 2; i++)
#pragma unroll
        for (int j = 0; j < 4; j++)
#pragma unroll
            for (int k = 0; k < 4; k++) d[i][j][k] = 0.f;

    load_chunk(0, 0);
    load_chunk(1, 1);

    for (int c = 0; c < NC; c++) {
        if (c < NC - 1) CP_WAIT1(); else CP_WAIT0();
        __syncthreads();
        if (c + 2 < NC) load_chunk(c + 2, (c + 2) % 3);

        const uint32_t base = sb + (c % 3) * STAGEB;
#pragma unroll
        for (int ks = 0; ks < 4; ks++) {
            uint32_t ah[2][4], al[2][4], bh[2][4], bl[2][4];
#pragma unroll
            for (int mt = 0; mt < 2; mt++) {
                int row = arow + mt * 16;
                uint32_t addr = base + row * 128 + (((ks * 2 + cA) ^ (row & 7)) << 4);
                ldm_x4(ah[mt], addr);
                ldm_x4(al[mt], addr + OFF_ALO);
            }
#pragma unroll
            for (int np = 0; np < 2; np++) {
                int row = brow + np * 16;
                uint32_t addr = base + OFF_BHI + row * 128 +
                                (((ks * 2 + cB) ^ (row & 7)) << 4);
                ldm_x4(bh[np], addr);
                ldm_x4(bl[np], addr + (OFF_BLO - OFF_BHI));
            }
            // term-major ordering: consecutive MMAs hit different accumulators
#pragma unroll
            for (int mt = 0; mt < 2; mt++)
#pragma unroll
                for (int np = 0; np < 2; np++)
#pragma unroll
                    for (int s = 0; s < 2; s++)
                        mma_bf16(d[mt][np * 2 + s], ah[mt], bh[np][2 * s], bh[np][2 * s + 1]);
#pragma unroll
            for (int mt = 0; mt < 2; mt++)
#pragma unroll
                for (int np = 0; np < 2; np++)
#pragma unroll
                    for (int s = 0; s < 2; s++)
                        mma_bf16(d[mt][np * 2 + s], ah[mt], bl[np][2 * s], bl[np][2 * s + 1]);
#pragma unroll
            for (int mt = 0; mt < 2; mt++)
#pragma unroll
                for (int np = 0; np < 2; np++)
#pragma unroll
                    for (int s = 0; s < 2; s++)
                        mma_bf16(d[mt][np * 2 + s], al[mt], bh[np][2 * s], bh[np][2 * s + 1]);
        }
        __syncthreads();
    }

    const int colb = (lane & 3) * 2;
    if (!qkv) {
#pragma unroll
        for (int mt = 0; mt < 2; mt++) {
            int r = m0 + wm + mt * 16 + (lane >> 2);
#pragma unroll
            for (int nt = 0; nt < 4; nt++) {
                int col = n0 + wn + nt * 8 + colb;
                *(float2*)(C + (size_t)r * N + col)       = make_float2(d[mt][nt][0], d[mt][nt][1]);
                *(float2*)(C + (size_t)(r + 8) * N + col) = make_float2(d[mt][nt][2], d[mt][nt][3]);
            }
        }
    } else {
        // fused epilogue: Q (rope+scale, fp16), K (rope, fp16), V (fp16)
        const int mode = (n0 < 2048) ? 0 : (n0 < 2560 ? 1 : 2);
        const float qscale = 0.0883883476483184f;
#pragma unroll
        for (int mt = 0; mt < 2; mt++) {
            int r = m0 + wm + mt * 16 + (lane >> 2);
#pragma unroll
            for (int nt = 0; nt < 4; nt++) {
                int col = n0 + wn + nt * 8 + colb;
                float c00 = d[mt][nt][0], c01 = d[mt][nt][1];
                float c10 = d[mt][nt][2], c11 = d[mt][nt][3];
                if (mode == 2) {
                    int cv = col - 2560;
                    *(__half2*)(h_V + (size_t)r * 512 + cv)       = __floats2half2_rn(c00, c01);
                    *(__half2*)(h_V + (size_t)(r + 8) * 512 + cv) = __floats2half2_rn(c10, c11);
                } else {
                    int cl = (mode == 0) ? col : col - 2048;
                    int i = (cl & 127) >> 1;
                    float2 t0 = g_rope[r * 64 + i];
                    float2 t1 = g_rope[(r + 8) * 64 + i];
                    float s = (mode == 0) ? qscale : 1.0f;
                    float o00 = (c00 * t0.x - c01 * t0.y) * s;
                    float o01 = (c00 * t0.y + c01 * t0.x) * s;
                    float o10 = (c10 * t1.x - c11 * t1.y) * s;
                    float o11 = (c10 * t1.y + c11 * t1.x) * s;
                    if (mode == 0) {
                        *(__half2*)(h_Q + (size_t)r * 2048 + cl)       = __floats2half2_rn(o00, o01);
                        *(__half2*)(h_Q + (size_t)(r + 8) * 2048 + cl) = __floats2half2_rn(o10, o11);
                    } else {
                        *(__half2*)(h_K + (size_t)r * 512 + cl)       = __floats2half2_rn(o00, o01);
                        *(__half2*)(h_K + (size_t)(r + 8) * 512 + cl) = __floats2half2_rn(o10, o11);
                    }
                }
            }
        }
    }
}

// ---------------------------------------------------------------------------
// conversions
// ---------------------------------------------------------------------------
__global__ void cvt_split(const float* __restrict__ in,
                          __nv_bfloat16* __restrict__ hi,
                          __nv_bfloat16* __restrict__ lo, int n2)
{
    int i = blockIdx.x * blockDim.x + threadIdx.x;
    if (i >= n2) return;
    float2 v = ((const float2*)in)[i];
    __nv_bfloat16 hx = __float2bfloat16(v.x);
    __nv_bfloat16 hy = __float2bfloat16(v.y);
    __nv_bfloat162 h; h.x = hx; h.y = hy;
    __nv_bfloat162 l;
    l.x = __float2bfloat16(v.x - __bfloat162float(hx));
    l.y = __float2bfloat16(v.y - __bfloat162float(hy));
    ((__nv_bfloat162*)hi)[i] = h;
    ((__nv_bfloat162*)lo)[i] = l;
}

__global__ void cvt_split_T(const float* __restrict__ W,
                            __nv_bfloat16* __restrict__ hi,
                            __nv_bfloat16* __restrict__ lo, int K, int N)
{
    __shared__ float t[32][33];
    int x = blockIdx.x * 32 + threadIdx.x;
    int y = blockIdx.y * 32 + threadIdx.y;
#pragma unroll
    for (int j = 0; j < 32; j += 8)
        t[threadIdx.y + j][threadIdx.x] = W[(size_t)(y + j) * N + x];
    __syncthreads();
    int x2 = blockIdx.y * 32 + threadIdx.x;
    int y2 = blockIdx.x * 32 + threadIdx.y;
#pragma unroll
    for (int j = 0; j < 32; j += 8) {
        float v = t[threadIdx.x][threadIdx.y + j];
        __nv_bfloat16 h = __float2bfloat16(v);
        hi[(size_t)(y2 + j) * K + x2] = h;
        lo[(size_t)(y2 + j) * K + x2] = __float2bfloat16(v - __bfloat162float(h));
    }
}

// precompute rope cos/sin table [S][64]
__global__ void rope_tab(const int* __restrict__ pos, int S)
{
    int idx = blockIdx.x * blockDim.x + threadIdx.x;
    if (idx >= S * 64) return;
    int i = idx & 63, s = idx >> 6;
    float freq = exp2f(-(float)(2 * i) * (1.0f / 128.0f) * 13.287712379549449f);
    float ang = (float)pos[s] * freq;
    float sn, cs;
    sincosf(ang, &sn, &cs);
    g_rope[idx] = make_float2(cs, sn);
}

// ---------------------------------------------------------------------------
// fp16 mma.sync flash attention. 128 threads (4 warps), BQ=64, KV tiles of 64.
// Epilogue writes bf16 hi/lo split directly into g_Ahi/g_Alo.
// ---------------------------------------------------------------------------
#define ATSTR 272
#define AT_K  17408
#define AT_V  52224
#define AT_MC 87040
#define AT_SMEM 87552

__global__ __launch_bounds__(128, 2) void attn_mma(
    const int* __restrict__ amask, const int* __restrict__ segs)
{
    extern __shared__ char sm[];
    const uint32_t sb = smem_u32(sm);
    const int tid = threadIdx.x, lane = tid & 31, wid = tid >> 5;
    const int h = blockIdx.y;
    const int qb = (int)gridDim.x - 1 - (int)blockIdx.x;   // long blocks first
    const int q0 = qb * 64;
    const int kvh = h >> 2;
    const int ntile = qb + 1;

    auto prefetch = [&](int t) {
        int k0 = t * 64;
        int buf = t & 1;
#pragma unroll
        for (int it = 0; it < 8; it++) {
            int idx = tid + it * 128;
            int row = idx >> 4, ch = idx & 15;
            cp_async16(sb + AT_K + buf * (64 * ATSTR) + row * ATSTR + ch * 16,
                       h_K + ((size_t)(k0 + row) * NKV + kvh) * HD + ch * 8);
            cp_async16(sb + AT_V + buf * (64 * ATSTR) + row * ATSTR + ch * 16,
                       h_V + ((size_t)(k0 + row) * NKV + kvh) * HD + ch * 8);
        }
        if (tid < 64) {
            int a = amask[k0 + tid];
            ((int*)(sm + AT_MC))[buf * 64 + tid] =
                (a > 0) ? segs[k0 + tid] : 0x7fffffff;
        }
        CP_COMMIT();
    };

#pragma unroll
    for (int it = 0; it < 8; it++) {
        int idx = tid + it * 128;
        int row = idx >> 4, ch = idx & 15;
        cp_async16(sb + row * ATSTR + ch * 16,
                   h_Q + ((size_t)(q0 + row) * NH + h) * HD + ch * 8);
    }
    prefetch(0);

    const int qr0 = q0 + wid * 16 + (lane >> 2);
    const int qr1 = qr0 + 8;
    const int qseg0 = segs[qr0];
    const int qseg1 = segs[qr1];
    const int colb = (lane & 3) * 2;

    float o[16][4];
#pragma unroll
    for (int j = 0; j < 16; j++)
#pragma unroll
        for (int k = 0; k < 4; k++) o[j][k] = 0.f;
    float m0 = -1e30f, m1 = -1e30f, l0 = 0.f, l1 = 0.f;
    uint32_t qf[8][4];

    for (int t = 0; t < ntile; t++) {
        const int k0 = t * 64;
        const int buf = t & 1;
        if (t + 1 < ntile) { prefetch(t + 1); CP_WAIT1(); }
        else               { CP_WAIT0(); }
        __syncthreads();

        if (t == 0) {
#pragma unroll
            for (int ks = 0; ks < 8; ks++) {
                uint32_t addr = sb + (wid * 16 + (lane & 15)) * ATSTR +
                                (ks * 16 + (lane >> 4) * 8) * 2;
                ldm_x4(qf[ks], addr);
            }
        }

        float sf[8][4];
#pragma unroll
        for (int j = 0; j < 8; j++)
#pragma unroll
            for (int k = 0; k < 4; k++) sf[j][k] = 0.f;

        const uint32_t kb = sb + AT_K + buf * (64 * ATSTR);
#pragma unroll
        for (int ks = 0; ks < 8; ks++) {
            uint32_t bk[4][4];
#pragma unroll
            for (int np = 0; np < 4; np++) {
                uint32_t addr = kb + (np * 16 + ((lane >> 4) << 3) + (lane & 7)) * ATSTR +
                                (ks * 16 + ((lane >> 3) & 1) * 8) * 2;
                ldm_x4(bk[np], addr);
            }
#pragma unroll
            for (int np = 0; np < 4; np++)
#pragma unroll
                for (int s = 0; s < 2; s++)
                    mma_f16(sf[np * 2 + s], qf[ks], bk[np][2 * s], bk[np][2 * s + 1]);
        }

        const int* kc = (const int*)(sm + AT_MC) + buf * 64;
#pragma unroll
        for (int j = 0; j < 8; j++) {
            int c0 = j * 8 + colb, c1 = c0 + 1;
            int kp0 = k0 + c0, kp1 = k0 + c1;
            int kc0 = kc[c0], kc1 = kc[c1];
            if (!(kp0 <= qr0 && kc0 == qseg0)) sf[j][0] = -1e30f;
            if (!(kp1 <= qr0 && kc1 == qseg0)) sf[j][1] = -1e30f;
            if (!(kp0 <= qr1 && kc0 == qseg1)) sf[j][2] = -1e30f;
            if (!(kp1 <= qr1 && kc1 == qseg1)) sf[j][3] = -1e30f;
        }

        float mx0 = -1e30f, mx1 = -1e30f;
#pragma unroll
        for (int j = 0; j < 8; j++) {
            mx0 = fmaxf(mx0, fmaxf(sf[j][0], sf[j][1]));
            mx1 = fmaxf(mx1, fmaxf(sf[j][2], sf[j][3]));
        }
        mx0 = fmaxf(mx0, __shfl_xor_sync(0xffffffffu, mx0, 1));
        mx0 = fmaxf(mx0, __shfl_xor_sync(0xffffffffu, mx0, 2));
        mx1 = fmaxf(mx1, __shfl_xor_sync(0xffffffffu, mx1, 1));
        mx1 = fmaxf(mx1, __shfl_xor_sync(0xffffffffu, mx1, 2));
        float mn0 = fmaxf(m0, mx0), mn1 = fmaxf(m1, mx1);
        float a0 = __expf(m0 - mn0), a1 = __expf(m1 - mn1);
        m0 = mn0; m1 = mn1;
        float s0 = 0.f, s1 = 0.f;
#pragma unroll
        for (int j = 0; j < 8; j++) {
            sf[j][0] = __expf(sf[j][0] - mn0);
            sf[j][1] = __expf(sf[j][1] - mn0);
            sf[j][2] = __expf(sf[j][2] - mn1);
            sf[j][3] = __expf(sf[j][3] - mn1);
            s0 += sf[j][0] + sf[j][1];
            s1 += sf[j][2] + sf[j][3];
        }
        s0 += __shfl_xor_sync(0xffffffffu, s0, 1);
        s0 += __shfl_xor_sync(0xffffffffu, s0, 2);
        s1 += __shfl_xor_sync(0xffffffffu, s1, 1);
        s1 += __shfl_xor_sync(0xffffffffu, s1, 2);
        l0 = l0 * a0 + s0;
        l1 = l1 * a1 + s1;
#pragma unroll
        for (int j = 0; j < 16; j++) {
            o[j][0] *= a0; o[j][1] *= a0;
            o[j][2] *= a1; o[j][3] *= a1;
        }

        uint32_t pa[4][4];
#pragma unroll
        for (int kk = 0; kk < 4; kk++) {
            pa[kk][0] = h2_as_u32(__floats2half2_rn(sf[2 * kk][0], sf[2 * kk][1]));
            pa[kk][1] = h2_as_u32(__floats2half2_rn(sf[2 * kk][2], sf[2 * kk][3]));
            pa[kk][2] = h2_as_u32(__floats2half2_rn(sf[2 * kk + 1][0], sf[2 * kk + 1][1]));
            pa[kk][3] = h2_as_u32(__floats2half2_rn(sf[2 * kk + 1][2], sf[2 * kk + 1][3]));
        }

        const uint32_t vb = sb + AT_V + buf * (64 * ATSTR);
#pragma unroll
        for (int ks = 0; ks < 4; ks++) {
            uint32_t bv[8][4];
#pragma unroll
            for (int nb = 0; nb < 8; nb++) {
                uint32_t addr = vb + (ks * 16 + (lane & 15)) * ATSTR +
                                (nb * 16 + (lane >> 4) * 8) * 2;
                ldm_x4_t(bv[nb], addr);
            }
#pragma unroll
            for (int nb = 0; nb < 8; nb++)
#pragma unroll
                for (int s = 0; s < 2; s++)
                    mma_f16(o[nb * 2 + s], pa[ks], bv[nb][2 * s], bv[nb][2 * s + 1]);
        }
        __syncthreads();
    }

    // epilogue: normalize + bf16 hi/lo split directly into g_Ahi/g_Alo
    float inv0 = (l0 > 0.f) ? 1.f / l0 : 0.f;
    float inv1 = (l1 > 0.f) ? 1.f / l1 : 0.f;
#pragma unroll
    for (int j = 0; j < 16; j++) {
        int col = h * HD + j * 8 + colb;
        float v00 = o[j][0] * inv0, v01 = o[j][1] * inv0;
        float v10 = o[j][2] * inv1, v11 = o[j][3] * inv1;
        __nv_bfloat162 hi0, lo0, hi1, lo1;
        hi0.x = __float2bfloat16(v00); lo0.x = __float2bfloat16(v00 - __bfloat162float(hi0.x));
        hi0.y = __float2bfloat16(v01); lo0.y = __float2bfloat16(v01 - __bfloat162float(hi0.y));
        hi1.x = __float2bfloat16(v10); lo1.x = __float2bfloat16(v10 - __bfloat162float(hi1.x));
        hi1.y = __float2bfloat16(v11); lo1.y = __float2bfloat16(v11 - __bfloat162float(hi1.y));
        *(__nv_bfloat162*)(g_Ahi + (size_t)qr0 * 2048 + col) = hi0;
        *(__nv_bfloat162*)(g_Alo + (size_t)qr0 * 2048 + col) = lo0;
        *(__nv_bfloat162*)(g_Ahi + (size_t)qr1 * 2048 + col) = hi1;
        *(__nv_bfloat162*)(g_Alo + (size_t)qr1 * 2048 + col) = lo1;
    }
}

// ---------------------------------------------------------------------------
// Host launcher
// ---------------------------------------------------------------------------
extern "C" void kernel_launch(void* const* d_in, const int* in_sizes, int n_in,
                              void* d_out, int out_size)
{
    const float* X     = (const float*)d_in[0];
    const int*   amask = (const int*)d_in[1];
    const int*   segs  = (const int*)d_in[2];
    const int*   pos   = (const int*)d_in[3];
    const float* Wq    = (const float*)d_in[4];
    const float* Wk    = (const float*)d_in[5];
    const float* Wv    = (const float*)d_in[6];
    const float* Wo    = (const float*)d_in[7];
    float* out = (float*)d_out;

    const int S   = in_sizes[3];
    const int H   = in_sizes[0] / S;        // 2048
    const int Hkv = in_sizes[5] / H;        // 512

    __nv_bfloat16 *Ahi, *Alo, *Bhi, *Blo;
    cudaGetSymbolAddress((void**)&Ahi, g_Ahi);
    cudaGetSymbolAddress((void**)&Alo, g_Alo);
    cudaGetSymbolAddress((void**)&Bhi, g_Bhi);
    cudaGetSymbolAddress((void**)&Blo, g_Blo);

    const int gemm_smem = 3 * STAGEB;   // 192KB
    cudaFuncSetAttribute(gemm_mma, cudaFuncAttributeMaxDynamicSharedMemorySize,
                         gemm_smem);
    cudaFuncSetAttribute(attn_mma, cudaFuncAttributeMaxDynamicSharedMemorySize,
                         AT_SMEM);

    const int n2 = (S * H) / 2;
    // split X into bf16 hi/lo
    cvt_split<<<(n2 + 255) / 256, 256>>>(X, Ahi, Alo, n2);
    // pack Wq|Wk|Wv transposed into B[3072][2048]
    cvt_split_T<<<dim3(H / 32, H / 32), dim3(32, 8)>>>(Wq, Bhi, Blo, H, H);
    cvt_split_T<<<dim3(Hkv / 32, H / 32), dim3(32, 8)>>>(Wk, Bhi + (size_t)2048 * KDIM,
                                                         Blo + (size_t)2048 * KDIM, H, Hkv);
    cvt_split_T<<<dim3(Hkv / 32, H / 32), dim3(32, 8)>>>(Wv, Bhi + (size_t)2560 * KDIM,
                                                         Blo + (size_t)2560 * KDIM, H, Hkv);
    // rope table
    rope_tab<<<(S * 64 + 255) / 256, 256>>>(pos, S);

    // fused QKV GEMM with rope/fp16 epilogue
    gemm_mma<<<dim3(3072 / 128, S / 128), 512, gemm_smem>>>(nullptr, 3072, 1);

    // fp16 tensor-core flash attention (writes bf16 split to g_Ahi/g_Alo)
    attn_mma<<<dim3(S / 64, NH), 128, AT_SMEM>>>(amask, segs);

    // out = A @ Wo
    cvt_split_T<<<dim3(H / 32, H / 32), dim3(32, 8)>>>(Wo, Bhi, Blo, H, H);
    gemm_mma<<<dim3(H / 128, S / 128), 512, gemm_smem>>>(out, H, 0);
}

// round 7
// speedup vs baseline: 7.7477x; 1.6849x over previous
#include <cuda_runtime.h>
#include <cuda_bf16.h>
#include <cuda_fp16.h>
#include <math.h>
#include <stdint.h>

#define NH   16
#define NKV  4
#define HD   128
#define SMAX 2048
#define KDIM 2048

// ---------------- scratch (device globals; no allocation allowed) ----------
__device__ __align__(256) __half g_Ah[SMAX * KDIM];
__device__ __align__(256) __half g_Bh[3072 * KDIM];
__device__ __align__(256) __half h_Q[SMAX * NH * HD];
__device__ __align__(256) __half h_K[SMAX * NKV * HD];
__device__ __align__(256) __half h_V[SMAX * NKV * HD];
__device__ __align__(256) float2 g_rope[SMAX * 64];

#define WSCALE 256.0f
#define INVW   0.00390625f

// ---------------- helpers --------------------------------------------------
__device__ __forceinline__ uint32_t smem_u32(const void* p) {
    uint32_t a;
    asm("{ .reg .u64 t; cvta.to.shared.u64 t, %1; cvt.u32.u64 %0, t; }"
        : "=r"(a) : "l"(p));
    return a;
}
__device__ __forceinline__ uint32_t h2_as_u32(__half2 h) {
    return *reinterpret_cast<uint32_t*>(&h);
}
__device__ __forceinline__ void ldm_x4(uint32_t* r, uint32_t addr) {
    asm volatile("ldmatrix.sync.aligned.m8n8.x4.shared.b16 {%0,%1,%2,%3}, [%4];"
                 : "=r"(r[0]), "=r"(r[1]), "=r"(r[2]), "=r"(r[3]) : "r"(addr));
}
__device__ __forceinline__ void ldm_x4_t(uint32_t* r, uint32_t addr) {
    asm volatile("ldmatrix.sync.aligned.m8n8.x4.trans.shared.b16 {%0,%1,%2,%3}, [%4];"
                 : "=r"(r[0]), "=r"(r[1]), "=r"(r[2]), "=r"(r[3]) : "r"(addr));
}
__device__ __forceinline__ void mma_f16(float* d, const uint32_t* a,
                                        uint32_t b0, uint32_t b1) {
    asm volatile(
        "mma.sync.aligned.m16n8k16.row.col.f32.f16.f16.f32 "
        "{%0,%1,%2,%3}, {%4,%5,%6,%7}, {%8,%9}, {%0,%1,%2,%3};"
        : "+f"(d[0]), "+f"(d[1]), "+f"(d[2]), "+f"(d[3])
        : "r"(a[0]), "r"(a[1]), "r"(a[2]), "r"(a[3]), "r"(b0), "r"(b1));
}
__device__ __forceinline__ void cp_async16(uint32_t dst, const void* src) {
    asm volatile("cp.async.cg.shared.global [%0], [%1], 16;"
                 :: "r"(dst), "l"(src) : "memory");
}
#define CP_COMMIT() asm volatile("cp.async.commit_group;" ::: "memory")
#define CP_WAIT0()  asm volatile("cp.async.wait_group 0;" ::: "memory")
#define CP_WAIT1()  asm volatile("cp.async.wait_group 1;" ::: "memory")

// ---------------------------------------------------------------------------
// fp16 GEMM via mma.sync. A = g_Ah [2048][2048], B = g_Bh [N][2048] (x256).
// CTA 128x128, BK=64, 3-stage cp.async pipeline, 16 warps (4x4 of 32x32).
// qkv=0: C fp32 (x 1/256).  qkv=1: fused rope/scale/fp16 epilogue -> h_Q/K/V.
// ---------------------------------------------------------------------------
#define NC      (KDIM / 64)
#define STAGEB  32768
#define OFF_B   16384

__global__ __launch_bounds__(512, 1) void gemm_mma(float* __restrict__ C,
                                                   int N, int qkv)
{
    extern __shared__ char smem[];
    const uint32_t sb = smem_u32(smem);
    const int tid = threadIdx.x, lane = tid & 31, wid = tid >> 5;
    const int m0 = blockIdx.y * 128, n0 = blockIdx.x * 128;
    const int wm = (wid >> 2) * 32, wn = (wid & 3) * 32;

    auto load_op = [&](const __half* src, int rowbase, uint32_t dstbase, int c) {
#pragma unroll
        for (int it = 0; it < 2; it++) {
            int idx = tid + it * 512;
            int row = idx >> 3, ch = idx & 7;
            const void* g = src + (size_t)(rowbase + row) * KDIM + c * 64 + ch * 8;
            uint32_t dst = dstbase + row * 128 + ((ch ^ (row & 7)) << 4);
            cp_async16(dst, g);
        }
    };
    auto load_chunk = [&](int c, int buf) {
        uint32_t base = sb + buf * STAGEB;
        load_op(g_Ah, m0, base, c);
        load_op(g_Bh, n0, base + OFF_B, c);
        CP_COMMIT();
    };

    const int arow = wm + (lane & 15);
    const int cA   = lane >> 4;
    const int brow = wn + ((lane >> 4) << 3) + (lane & 7);
    const int cB   = (lane >> 3) & 1;

    float d[2][4][4];
#pragma unroll
    for (int i = 0; i < 2; i++)
#pragma unroll
        for (int j = 0; j < 4; j++)
#pragma unroll
            for (int k = 0; k < 4; k++) d[i][j][k] = 0.f;

    load_chunk(0, 0);
    load_chunk(1, 1);

    for (int c = 0; c < NC; c++) {
        if (c < NC - 1) CP_WAIT1(); else CP_WAIT0();
        __syncthreads();
        if (c + 2 < NC) load_chunk(c + 2, (c + 2) % 3);

        const uint32_t base = sb + (c % 3) * STAGEB;
#pragma unroll
        for (int ks = 0; ks < 4; ks++) {
            uint32_t a[2][4], b[2][4];
#pragma unroll
            for (int mt = 0; mt < 2; mt++) {
                int row = arow + mt * 16;
                ldm_x4(a[mt], base + row * 128 + (((ks * 2 + cA) ^ (row & 7)) << 4));
            }
#pragma unroll
            for (int np = 0; np < 2; np++) {
                int row = brow + np * 16;
                ldm_x4(b[np], base + OFF_B + row * 128 +
                              (((ks * 2 + cB) ^ (row & 7)) << 4));
            }
#pragma unroll
            for (int mt = 0; mt < 2; mt++)
#pragma unroll
                for (int np = 0; np < 2; np++)
#pragma unroll
                    for (int s = 0; s < 2; s++)
                        mma_f16(d[mt][np * 2 + s], a[mt], b[np][2 * s], b[np][2 * s + 1]);
        }
        __syncthreads();
    }

    const int colb = (lane & 3) * 2;
    if (!qkv) {
#pragma unroll
        for (int mt = 0; mt < 2; mt++) {
            int r = m0 + wm + mt * 16 + (lane >> 2);
#pragma unroll
            for (int nt = 0; nt < 4; nt++) {
                int col = n0 + wn + nt * 8 + colb;
                *(float2*)(C + (size_t)r * N + col) =
                    make_float2(d[mt][nt][0] * INVW, d[mt][nt][1] * INVW);
                *(float2*)(C + (size_t)(r + 8) * N + col) =
                    make_float2(d[mt][nt][2] * INVW, d[mt][nt][3] * INVW);
            }
        }
    } else {
        const int mode = (n0 < 2048) ? 0 : (n0 < 2560 ? 1 : 2);
        const float qs = 0.0883883476483184f * INVW;
#pragma unroll
        for (int mt = 0; mt < 2; mt++) {
            int r = m0 + wm + mt * 16 + (lane >> 2);
#pragma unroll
            for (int nt = 0; nt < 4; nt++) {
                int col = n0 + wn + nt * 8 + colb;
                float c00 = d[mt][nt][0], c01 = d[mt][nt][1];
                float c10 = d[mt][nt][2], c11 = d[mt][nt][3];
                if (mode == 2) {
                    int cv = col - 2560;
                    *(__half2*)(h_V + (size_t)r * 512 + cv) =
                        __floats2half2_rn(c00 * INVW, c01 * INVW);
                    *(__half2*)(h_V + (size_t)(r + 8) * 512 + cv) =
                        __floats2half2_rn(c10 * INVW, c11 * INVW);
                } else {
                    int cl = (mode == 0) ? col : col - 2048;
                    int i = (cl & 127) >> 1;
                    float2 t0 = g_rope[r * 64 + i];
                    float2 t1 = g_rope[(r + 8) * 64 + i];
                    float s = (mode == 0) ? qs : INVW;
                    float o00 = (c00 * t0.x - c01 * t0.y) * s;
                    float o01 = (c00 * t0.y + c01 * t0.x) * s;
                    float o10 = (c10 * t1.x - c11 * t1.y) * s;
                    float o11 = (c10 * t1.y + c11 * t1.x) * s;
                    if (mode == 0) {
                        *(__half2*)(h_Q + (size_t)r * 2048 + cl)       = __floats2half2_rn(o00, o01);
                        *(__half2*)(h_Q + (size_t)(r + 8) * 2048 + cl) = __floats2half2_rn(o10, o11);
                    } else {
                        *(__half2*)(h_K + (size_t)r * 512 + cl)       = __floats2half2_rn(o00, o01);
                        *(__half2*)(h_K + (size_t)(r + 8) * 512 + cl) = __floats2half2_rn(o10, o11);
                    }
                }
            }
        }
    }
}

// ---------------------------------------------------------------------------
// conversions
// ---------------------------------------------------------------------------
__global__ void cvt_h(const float* __restrict__ in, __half* __restrict__ out, int n2)
{
    int i = blockIdx.x * blockDim.x + threadIdx.x;
    if (i >= n2) return;
    float2 v = ((const float2*)in)[i];
    ((__half2*)out)[i] = __floats2half2_rn(v.x, v.y);
}

__global__ void cvt_T_h(const float* __restrict__ W, __half* __restrict__ out,
                        int K, int N)
{
    __shared__ float t[32][33];
    int x = blockIdx.x * 32 + threadIdx.x;
    int y = blockIdx.y * 32 + threadIdx.y;
#pragma unroll
    for (int j = 0; j < 32; j += 8)
        t[threadIdx.y + j][threadIdx.x] = W[(size_t)(y + j) * N + x];
    __syncthreads();
    int x2 = blockIdx.y * 32 + threadIdx.x;
    int y2 = blockIdx.x * 32 + threadIdx.y;
#pragma unroll
    for (int j = 0; j < 32; j += 8)
        out[(size_t)(y2 + j) * K + x2] = __float2half_rn(t[threadIdx.x][threadIdx.y + j] * WSCALE);
}

__global__ void rope_tab(const int* __restrict__ pos, int S)
{
    int idx = blockIdx.x * blockDim.x + threadIdx.x;
    if (idx >= S * 64) return;
    int i = idx & 63, s = idx >> 6;
    float freq = exp2f(-(float)(2 * i) * (1.0f / 128.0f) * 13.287712379549449f);
    float ang = (float)pos[s] * freq;
    float sn, cs;
    sincosf(ang, &sn, &cs);
    g_rope[idx] = make_float2(cs, sn);
}

// ---------------------------------------------------------------------------
// fp16 mma.sync flash attention. 128 threads (4 warps), BQ=64, KV tiles of 64.
// Epilogue writes fp16 A directly into g_Ah.
// ---------------------------------------------------------------------------
#define ATSTR 272
#define AT_K  17408
#define AT_V  52224
#define AT_MC 87040
#define AT_SMEM 87552

__global__ __launch_bounds__(128, 2) void attn_mma(
    const int* __restrict__ amask, const int* __restrict__ segs)
{
    extern __shared__ char sm[];
    const uint32_t sb = smem_u32(sm);
    const int tid = threadIdx.x, lane = tid & 31, wid = tid >> 5;
    const int h = blockIdx.y;
    const int qb = (int)gridDim.x - 1 - (int)blockIdx.x;   // long blocks first
    const int q0 = qb * 64;
    const int kvh = h >> 2;
    const int ntile = qb + 1;

    auto prefetch = [&](int t) {
        int k0 = t * 64;
        int buf = t & 1;
#pragma unroll
        for (int it = 0; it < 8; it++) {
            int idx = tid + it * 128;
            int row = idx >> 4, ch = idx & 15;
            cp_async16(sb + AT_K + buf * (64 * ATSTR) + row * ATSTR + ch * 16,
                       h_K + ((size_t)(k0 + row) * NKV + kvh) * HD + ch * 8);
            cp_async16(sb + AT_V + buf * (64 * ATSTR) + row * ATSTR + ch * 16,
                       h_V + ((size_t)(k0 + row) * NKV + kvh) * HD + ch * 8);
        }
        if (tid < 64) {
            int a = amask[k0 + tid];
            ((int*)(sm + AT_MC))[buf * 64 + tid] =
                (a > 0) ? segs[k0 + tid] : 0x7fffffff;
        }
        CP_COMMIT();
    };

#pragma unroll
    for (int it = 0; it < 8; it++) {
        int idx = tid + it * 128;
        int row = idx >> 4, ch = idx & 15;
        cp_async16(sb + row * ATSTR + ch * 16,
                   h_Q + ((size_t)(q0 + row) * NH + h) * HD + ch * 8);
    }
    prefetch(0);

    const int qr0 = q0 + wid * 16 + (lane >> 2);
    const int qr1 = qr0 + 8;
    const int qseg0 = segs[qr0];
    const int qseg1 = segs[qr1];
    const int colb = (lane & 3) * 2;

    float o[16][4];
#pragma unroll
    for (int j = 0; j < 16; j++)
#pragma unroll
        for (int k = 0; k < 4; k++) o[j][k] = 0.f;
    float m0 = -1e30f, m1 = -1e30f, l0 = 0.f, l1 = 0.f;
    uint32_t qf[8][4];

    for (int t = 0; t < ntile; t++) {
        const int k0 = t * 64;
        const int buf = t & 1;
        if (t + 1 < ntile) { prefetch(t + 1); CP_WAIT1(); }
        else               { CP_WAIT0(); }
        __syncthreads();

        if (t == 0) {
#pragma unroll
            for (int ks = 0; ks < 8; ks++) {
                uint32_t addr = sb + (wid * 16 + (lane & 15)) * ATSTR +
                                (ks * 16 + (lane >> 4) * 8) * 2;
                ldm_x4(qf[ks], addr);
            }
        }

        float sf[8][4];
#pragma unroll
        for (int j = 0; j < 8; j++)
#pragma unroll
            for (int k = 0; k < 4; k++) sf[j][k] = 0.f;

        const uint32_t kb = sb + AT_K + buf * (64 * ATSTR);
#pragma unroll
        for (int ks = 0; ks < 8; ks++) {
            uint32_t bk[4][4];
#pragma unroll
            for (int np = 0; np < 4; np++) {
                uint32_t addr = kb + (np * 16 + ((lane >> 4) << 3) + (lane & 7)) * ATSTR +
                                (ks * 16 + ((lane >> 3) & 1) * 8) * 2;
                ldm_x4(bk[np], addr);
            }
#pragma unroll
            for (int np = 0; np < 4; np++)
#pragma unroll
                for (int s = 0; s < 2; s++)
                    mma_f16(sf[np * 2 + s], qf[ks], bk[np][2 * s], bk[np][2 * s + 1]);
        }

        const int* kc = (const int*)(sm + AT_MC) + buf * 64;
#pragma unroll
        for (int j = 0; j < 8; j++) {
            int c0 = j * 8 + colb, c1 = c0 + 1;
            int kp0 = k0 + c0, kp1 = k0 + c1;
            int kc0 = kc[c0], kc1 = kc[c1];
            if (!(kp0 <= qr0 && kc0 == qseg0)) sf[j][0] = -1e30f;
            if (!(kp1 <= qr0 && kc1 == qseg0)) sf[j][1] = -1e30f;
            if (!(kp0 <= qr1 && kc0 == qseg1)) sf[j][2] = -1e30f;
            if (!(kp1 <= qr1 && kc1 == qseg1)) sf[j][3] = -1e30f;
        }

        float mx0 = -1e30f, mx1 = -1e30f;
#pragma unroll
        for (int j = 0; j < 8; j++) {
            mx0 = fmaxf(mx0, fmaxf(sf[j][0], sf[j][1]));
            mx1 = fmaxf(mx1, fmaxf(sf[j][2], sf[j][3]));
        }
        mx0 = fmaxf(mx0, __shfl_xor_sync(0xffffffffu, mx0, 1));
        mx0 = fmaxf(mx0, __shfl_xor_sync(0xffffffffu, mx0, 2));
        mx1 = fmaxf(mx1, __shfl_xor_sync(0xffffffffu, mx1, 1));
        mx1 = fmaxf(mx1, __shfl_xor_sync(0xffffffffu, mx1, 2));
        float mn0 = fmaxf(m0, mx0), mn1 = fmaxf(m1, mx1);
        float a0 = __expf(m0 - mn0), a1 = __expf(m1 - mn1);
        m0 = mn0; m1 = mn1;
        float s0 = 0.f, s1 = 0.f;
#pragma unroll
        for (int j = 0; j < 8; j++) {
            sf[j][0] = __expf(sf[j][0] - mn0);
            sf[j][1] = __expf(sf[j][1] - mn0);
            sf[j][2] = __expf(sf[j][2] - mn1);
            sf[j][3] = __expf(sf[j][3] - mn1);
            s0 += sf[j][0] + sf[j][1];
            s1 += sf[j][2] + sf[j][3];
        }
        s0 += __shfl_xor_sync(0xffffffffu, s0, 1);
        s0 += __shfl_xor_sync(0xffffffffu, s0, 2);
        s1 += __shfl_xor_sync(0xffffffffu, s1, 1);
        s1 += __shfl_xor_sync(0xffffffffu, s1, 2);
        l0 = l0 * a0 + s0;
        l1 = l1 * a1 + s1;
#pragma unroll
        for (int j = 0; j < 16; j++) {
            o[j][0] *= a0; o[j][1] *= a0;
            o[j][2] *= a1; o[j][3] *= a1;
        }

        uint32_t pa[4][4];
#pragma unroll
        for (int kk = 0; kk < 4; kk++) {
            pa[kk][0] = h2_as_u32(__floats2half2_rn(sf[2 * kk][0], sf[2 * kk][1]));
            pa[kk][1] = h2_as_u32(__floats2half2_rn(sf[2 * kk][2], sf[2 * kk][3]));
            pa[kk][2] = h2_as_u32(__floats2half2_rn(sf[2 * kk + 1][0], sf[2 * kk + 1][1]));
            pa[kk][3] = h2_as_u32(__floats2half2_rn(sf[2 * kk + 1][2], sf[2 * kk + 1][3]));
        }

        const uint32_t vb = sb + AT_V + buf * (64 * ATSTR);
#pragma unroll
        for (int ks = 0; ks < 4; ks++) {
            uint32_t bv[8][4];
#pragma unroll
            for (int nb = 0; nb < 8; nb++) {
                uint32_t addr = vb + (ks * 16 + (lane & 15)) * ATSTR +
                                (nb * 16 + (lane >> 4) * 8) * 2;
                ldm_x4_t(bv[nb], addr);
            }
#pragma unroll
            for (int nb = 0; nb < 8; nb++)
#pragma unroll
                for (int s = 0; s < 2; s++)
                    mma_f16(o[nb * 2 + s], pa[ks], bv[nb][2 * s], bv[nb][2 * s + 1]);
        }
        __syncthreads();
    }

    float inv0 = (l0 > 0.f) ? 1.f / l0 : 0.f;
    float inv1 = (l1 > 0.f) ? 1.f / l1 : 0.f;
#pragma unroll
    for (int j = 0; j < 16; j++) {
        int col = h * HD + j * 8 + colb;
        *(__half2*)(g_Ah + (size_t)qr0 * 2048 + col) =
            __floats2half2_rn(o[j][0] * inv0, o[j][1] * inv0);
        *(__half2*)(g_Ah + (size_t)qr1 * 2048 + col) =
            __floats2half2_rn(o[j][2] * inv1, o[j][3] * inv1);
    }
}

// ---------------------------------------------------------------------------
// Host launcher
// ---------------------------------------------------------------------------
extern "C" void kernel_launch(void* const* d_in, const int* in_sizes, int n_in,
                              void* d_out, int out_size)
{
    const float* X     = (const float*)d_in[0];
    const int*   amask = (const int*)d_in[1];
    const int*   segs  = (const int*)d_in[2];
    const int*   pos   = (const int*)d_in[3];
    const float* Wq    = (const float*)d_in[4];
    const float* Wk    = (const float*)d_in[5];
    const float* Wv    = (const float*)d_in[6];
    const float* Wo    = (const float*)d_in[7];
    float* out = (float*)d_out;

    const int S   = in_sizes[3];
    const int H   = in_sizes[0] / S;        // 2048
    const int Hkv = in_sizes[5] / H;        // 512

    __half *Ah, *Bh;
    cudaGetSymbolAddress((void**)&Ah, g_Ah);
    cudaGetSymbolAddress((void**)&Bh, g_Bh);

    const int gemm_smem = 3 * STAGEB;   // 96KB
    cudaFuncSetAttribute(gemm_mma, cudaFuncAttributeMaxDynamicSharedMemorySize,
                         gemm_smem);
    cudaFuncSetAttribute(attn_mma, cudaFuncAttributeMaxDynamicSharedMemorySize,
                         AT_SMEM);

    const int n2 = (S * H) / 2;
    // X -> fp16
    cvt_h<<<(n2 + 255) / 256, 256>>>(X, Ah, n2);
    // pack Wq|Wk|Wv transposed (x256) into B[3072][2048]
    cvt_T_h<<<dim3(H / 32, H / 32), dim3(32, 8)>>>(Wq, Bh, H, H);
    cvt_T_h<<<dim3(Hkv / 32, H / 32), dim3(32, 8)>>>(Wk, Bh + (size_t)2048 * KDIM, H, Hkv);
    cvt_T_h<<<dim3(Hkv / 32, H / 32), dim3(32, 8)>>>(Wv, Bh + (size_t)2560 * KDIM, H, Hkv);
    rope_tab<<<(S * 64 + 255) / 256, 256>>>(pos, S);

    // fused QKV GEMM with rope/fp16 epilogue
    gemm_mma<<<dim3(3072 / 128, S / 128), 512, gemm_smem>>>(nullptr, 3072, 1);

    // fp16 tensor-core flash attention (writes fp16 A to g_Ah)
    attn_mma<<<dim3(S / 64, NH), 128, AT_SMEM>>>(amask, segs);

    // out = A @ Wo / 256
    cvt_T_h<<<dim3(H / 32, H / 32), dim3(32, 8)>>>(Wo, Bh, H, H);
    gemm_mma<<<dim3(H / 128, S / 128), 512, gemm_smem>>>(out, H, 0);
}

// round 8
// speedup vs baseline: 8.1169x; 1.0477x over previous
#include <cuda_runtime.h>
#include <cuda_bf16.h>
#include <cuda_fp16.h>
#include <math.h>
#include <stdint.h>

#define NH   16
#define NKV  4
#define HD   128
#define SMAX 2048
#define KDIM 2048

// ---------------- scratch (device globals; no allocation allowed) ----------
__device__ __align__(256) __half g_Ah[SMAX * KDIM];
__device__ __align__(256) __half g_Bh[3072 * KDIM];
__device__ __align__(256) __half h_Q[SMAX * NH * HD];
__device__ __align__(256) __half h_K[SMAX * NKV * HD];
__device__ __align__(256) __half h_V[SMAX * NKV * HD];
__device__ __align__(256) float2 g_rope[SMAX * 64];

#define WSCALE 256.0f
#define INVW   0.00390625f

// ---------------- helpers --------------------------------------------------
__device__ __forceinline__ uint32_t smem_u32(const void* p) {
    uint32_t a;
    asm("{ .reg .u64 t; cvta.to.shared.u64 t, %1; cvt.u32.u64 %0, t; }"
        : "=r"(a) : "l"(p));
    return a;
}
__device__ __forceinline__ uint32_t h2_as_u32(__half2 h) {
    return *reinterpret_cast<uint32_t*>(&h);
}
__device__ __forceinline__ void ldm_x4(uint32_t* r, uint32_t addr) {
    asm volatile("ldmatrix.sync.aligned.m8n8.x4.shared.b16 {%0,%1,%2,%3}, [%4];"
                 : "=r"(r[0]), "=r"(r[1]), "=r"(r[2]), "=r"(r[3]) : "r"(addr));
}
__device__ __forceinline__ void ldm_x4_t(uint32_t* r, uint32_t addr) {
    asm volatile("ldmatrix.sync.aligned.m8n8.x4.trans.shared.b16 {%0,%1,%2,%3}, [%4];"
                 : "=r"(r[0]), "=r"(r[1]), "=r"(r[2]), "=r"(r[3]) : "r"(addr));
}
__device__ __forceinline__ void mma_f16(float* d, const uint32_t* a,
                                        uint32_t b0, uint32_t b1) {
    asm volatile(
        "mma.sync.aligned.m16n8k16.row.col.f32.f16.f16.f32 "
        "{%0,%1,%2,%3}, {%4,%5,%6,%7}, {%8,%9}, {%0,%1,%2,%3};"
        : "+f"(d[0]), "+f"(d[1]), "+f"(d[2]), "+f"(d[3])
        : "r"(a[0]), "r"(a[1]), "r"(a[2]), "r"(a[3]), "r"(b0), "r"(b1));
}
__device__ __forceinline__ void cp_async16(uint32_t dst, const void* src) {
    asm volatile("cp.async.cg.shared.global [%0], [%1], 16;"
                 :: "r"(dst), "l"(src) : "memory");
}
#define CP_COMMIT() asm volatile("cp.async.commit_group;" ::: "memory")
#define CP_WAIT0()  asm volatile("cp.async.wait_group 0;" ::: "memory")
#define CP_WAIT1()  asm volatile("cp.async.wait_group 1;" ::: "memory")

// ---------------------------------------------------------------------------
// fp16 GEMM via mma.sync. A = g_Ah [2048][2048], B = g_Bh [N][2048] (x256).
// CTA 128x128, BK=64, 3-stage cp.async pipeline, 16 warps (4x4 of 32x32).
// qkv=0: C fp32 (x 1/256).  qkv=1: fused rope/scale/fp16 epilogue -> h_Q/K/V.
// ---------------------------------------------------------------------------
#define NC      (KDIM / 64)
#define STAGEB  32768
#define OFF_B   16384

__global__ __launch_bounds__(512, 1) void gemm_mma(float* __restrict__ C,
                                                   int N, int qkv)
{
    extern __shared__ char smem[];
    const uint32_t sb = smem_u32(smem);
    const int tid = threadIdx.x, lane = tid & 31, wid = tid >> 5;
    const int m0 = blockIdx.y * 128, n0 = blockIdx.x * 128;
    const int wm = (wid >> 2) * 32, wn = (wid & 3) * 32;

    auto load_op = [&](const __half* src, int rowbase, uint32_t dstbase, int c) {
#pragma unroll
        for (int it = 0; it < 2; it++) {
            int idx = tid + it * 512;
            int row = idx >> 3, ch = idx & 7;
            const void* g = src + (size_t)(rowbase + row) * KDIM + c * 64 + ch * 8;
            uint32_t dst = dstbase + row * 128 + ((ch ^ (row & 7)) << 4);
            cp_async16(dst, g);
        }
    };
    auto load_chunk = [&](int c, int buf) {
        uint32_t base = sb + buf * STAGEB;
        load_op(g_Ah, m0, base, c);
        load_op(g_Bh, n0, base + OFF_B, c);
        CP_COMMIT();
    };

    const int arow = wm + (lane & 15);
    const int cA   = lane >> 4;
    const int brow = wn + ((lane >> 4) << 3) + (lane & 7);
    const int cB   = (lane >> 3) & 1;

    float d[2][4][4];
#pragma unroll
    for (int i = 0; i < 2; i++)
#pragma unroll
        for (int j = 0; j < 4; j++)
#pragma unroll
            for (int k = 0; k < 4; k++) d[i][j][k] = 0.f;

    load_chunk(0, 0);
    load_chunk(1, 1);

    for (int c = 0; c < NC; c++) {
        if (c < NC - 1) CP_WAIT1(); else CP_WAIT0();
        __syncthreads();
        if (c + 2 < NC) load_chunk(c + 2, (c + 2) % 3);

        const uint32_t base = sb + (c % 3) * STAGEB;
#pragma unroll
        for (int ks = 0; ks < 4; ks++) {
            uint32_t a[2][4], b[2][4];
#pragma unroll
            for (int mt = 0; mt < 2; mt++) {
                int row = arow + mt * 16;
                ldm_x4(a[mt], base + row * 128 + (((ks * 2 + cA) ^ (row & 7)) << 4));
            }
#pragma unroll
            for (int np = 0; np < 2; np++) {
                int row = brow + np * 16;
                ldm_x4(b[np], base + OFF_B + row * 128 +
                              (((ks * 2 + cB) ^ (row & 7)) << 4));
            }
#pragma unroll
            for (int mt = 0; mt < 2; mt++)
#pragma unroll
                for (int np = 0; np < 2; np++)
#pragma unroll
                    for (int s = 0; s < 2; s++)
                        mma_f16(d[mt][np * 2 + s], a[mt], b[np][2 * s], b[np][2 * s + 1]);
        }
        __syncthreads();
    }

    const int colb = (lane & 3) * 2;
    if (!qkv) {
#pragma unroll
        for (int mt = 0; mt < 2; mt++) {
            int r = m0 + wm + mt * 16 + (lane >> 2);
#pragma unroll
            for (int nt = 0; nt < 4; nt++) {
                int col = n0 + wn + nt * 8 + colb;
                *(float2*)(C + (size_t)r * N + col) =
                    make_float2(d[mt][nt][0] * INVW, d[mt][nt][1] * INVW);
                *(float2*)(C + (size_t)(r + 8) * N + col) =
                    make_float2(d[mt][nt][2] * INVW, d[mt][nt][3] * INVW);
            }
        }
    } else {
        const int mode = (n0 < 2048) ? 0 : (n0 < 2560 ? 1 : 2);
        const float qs = 0.0883883476483184f * INVW;
#pragma unroll
        for (int mt = 0; mt < 2; mt++) {
            int r = m0 + wm + mt * 16 + (lane >> 2);
#pragma unroll
            for (int nt = 0; nt < 4; nt++) {
                int col = n0 + wn + nt * 8 + colb;
                float c00 = d[mt][nt][0], c01 = d[mt][nt][1];
                float c10 = d[mt][nt][2], c11 = d[mt][nt][3];
                if (mode == 2) {
                    int cv = col - 2560;
                    *(__half2*)(h_V + (size_t)r * 512 + cv) =
                        __floats2half2_rn(c00 * INVW, c01 * INVW);
                    *(__half2*)(h_V + (size_t)(r + 8) * 512 + cv) =
                        __floats2half2_rn(c10 * INVW, c11 * INVW);
                } else {
                    int cl = (mode == 0) ? col : col - 2048;
                    int i = (cl & 127) >> 1;
                    float2 t0 = g_rope[r * 64 + i];
                    float2 t1 = g_rope[(r + 8) * 64 + i];
                    float s = (mode == 0) ? qs : INVW;
                    float o00 = (c00 * t0.x - c01 * t0.y) * s;
                    float o01 = (c00 * t0.y + c01 * t0.x) * s;
                    float o10 = (c10 * t1.x - c11 * t1.y) * s;
                    float o11 = (c10 * t1.y + c11 * t1.x) * s;
                    if (mode == 0) {
                        *(__half2*)(h_Q + (size_t)r * 2048 + cl)       = __floats2half2_rn(o00, o01);
                        *(__half2*)(h_Q + (size_t)(r + 8) * 2048 + cl) = __floats2half2_rn(o10, o11);
                    } else {
                        *(__half2*)(h_K + (size_t)r * 512 + cl)       = __floats2half2_rn(o00, o01);
                        *(__half2*)(h_K + (size_t)(r + 8) * 512 + cl) = __floats2half2_rn(o10, o11);
                    }
                }
            }
        }
    }
}

// ---------------------------------------------------------------------------
// conversions
// ---------------------------------------------------------------------------
__global__ void cvt_h(const float* __restrict__ in, __half* __restrict__ out, int n4)
{
    int i = blockIdx.x * blockDim.x + threadIdx.x;
    if (i >= n4) return;
    float4 v = ((const float4*)in)[i];
    uint2 u;
    u.x = h2_as_u32(__floats2half2_rn(v.x, v.y));
    u.y = h2_as_u32(__floats2half2_rn(v.z, v.w));
    ((uint2*)out)[i] = u;
}

// single-matrix transpose+convert (used for Wo)
__global__ void cvt_T_h(const float* __restrict__ W, __half* __restrict__ out,
                        int K, int N)
{
    __shared__ float t[32][33];
    int x = blockIdx.x * 32 + threadIdx.x;
    int y = blockIdx.y * 32 + threadIdx.y;
#pragma unroll
    for (int j = 0; j < 32; j += 8)
        t[threadIdx.y + j][threadIdx.x] = W[(size_t)(y + j) * N + x];
    __syncthreads();
    int x2 = blockIdx.y * 32 + threadIdx.x;
    int y2 = blockIdx.x * 32 + threadIdx.y;
#pragma unroll
    for (int j = 0; j < 32; j += 8)
        out[(size_t)(y2 + j) * K + x2] = __float2half_rn(t[threadIdx.x][threadIdx.y + j] * WSCALE);
}

// merged Wq|Wk|Wv transpose+convert into g_Bh[3072][2048]
__global__ void cvt_T_h3(const float* __restrict__ Wq, const float* __restrict__ Wk,
                         const float* __restrict__ Wv)
{
    __shared__ float t[32][33];
    int bc = blockIdx.x * 32;              // output-row block (0..3071)
    const float* W; int n0, Nw;
    if (bc < 2048)      { W = Wq; n0 = 0;    Nw = 2048; }
    else if (bc < 2560) { W = Wk; n0 = 2048; Nw = 512;  }
    else                { W = Wv; n0 = 2560; Nw = 512;  }
    int x = bc - n0 + threadIdx.x;         // source col
    int y = blockIdx.y * 32 + threadIdx.y; // source row (K)
#pragma unroll
    for (int j = 0; j < 32; j += 8)
        t[threadIdx.y + j][threadIdx.x] = W[(size_t)(y + j) * Nw + x];
    __syncthreads();
    int x2 = blockIdx.y * 32 + threadIdx.x;    // K index
    int y2 = bc + threadIdx.y;                 // global out row
#pragma unroll
    for (int j = 0; j < 32; j += 8)
        g_Bh[(size_t)(y2 + j) * KDIM + x2] =
            __float2half_rn(t[threadIdx.x][threadIdx.y + j] * WSCALE);
}

__global__ void rope_tab(const int* __restrict__ pos, int S)
{
    int idx = blockIdx.x * blockDim.x + threadIdx.x;
    if (idx >= S * 64) return;
    int i = idx & 63, s = idx >> 6;
    float freq = exp2f(-(float)(2 * i) * (1.0f / 128.0f) * 13.287712379549449f);
    float ang = (float)pos[s] * freq;
    float sn, cs;
    sincosf(ang, &sn, &cs);
    g_rope[idx] = make_float2(cs, sn);
}

// ---------------------------------------------------------------------------
// fp16 mma.sync flash attention. 128 threads (4 warps), BQ=64, KV tiles of 64.
// Q is staged in the K-buffer-1 region (consumed into registers before
// prefetch(1) overwrites it) -> smem 70.1KB -> 3 CTAs/SM.
// Epilogue writes fp16 A directly into g_Ah.
// ---------------------------------------------------------------------------
#define ATSTR 272
#define AT_KB 17408          // per-buffer bytes; K1 region also stages Q
#define AT_V  34816
#define AT_MC 69632
#define AT_SMEM 70144

__global__ __launch_bounds__(128, 3) void attn_mma(
    const int* __restrict__ amask, const int* __restrict__ segs)
{
    extern __shared__ char sm[];
    const uint32_t sb = smem_u32(sm);
    const int tid = threadIdx.x, lane = tid & 31, wid = tid >> 5;
    const int h = blockIdx.y;
    const int qb = (int)gridDim.x - 1 - (int)blockIdx.x;   // long blocks first
    const int q0 = qb * 64;
    const int kvh = h >> 2;
    const int ntile = qb + 1;

    auto prefetch = [&](int t) {
        int k0 = t * 64;
        int buf = t & 1;
#pragma unroll
        for (int it = 0; it < 8; it++) {
            int idx = tid + it * 128;
            int row = idx >> 4, ch = idx & 15;
            cp_async16(sb + buf * AT_KB + row * ATSTR + ch * 16,
                       h_K + ((size_t)(k0 + row) * NKV + kvh) * HD + ch * 8);
            cp_async16(sb + AT_V + buf * AT_KB + row * ATSTR + ch * 16,
                       h_V + ((size_t)(k0 + row) * NKV + kvh) * HD + ch * 8);
        }
        if (tid < 64) {
            int a = amask[k0 + tid];
            ((int*)(sm + AT_MC))[buf * 64 + tid] =
                (a > 0) ? segs[k0 + tid] : 0x7fffffff;
        }
        CP_COMMIT();
    };

    // prologue: Q tile (into K-buffer-1 region) + tile 0 (into buffer 0)
#pragma unroll
    for (int it = 0; it < 8; it++) {
        int idx = tid + it * 128;
        int row = idx >> 4, ch = idx & 15;
        cp_async16(sb + AT_KB + row * ATSTR + ch * 16,
                   h_Q + ((size_t)(q0 + row) * NH + h) * HD + ch * 8);
    }
    prefetch(0);
    CP_WAIT0();
    __syncthreads();

    uint32_t qf[8][4];
#pragma unroll
    for (int ks = 0; ks < 8; ks++) {
        uint32_t addr = sb + AT_KB + (wid * 16 + (lane & 15)) * ATSTR +
                        (ks * 16 + (lane >> 4) * 8) * 2;
        ldm_x4(qf[ks], addr);
    }
    __syncthreads();   // all warps consumed Q before prefetch(1) overwrites it

    const int qr0 = q0 + wid * 16 + (lane >> 2);
    const int qr1 = qr0 + 8;
    const int qseg0 = segs[qr0];
    const int qseg1 = segs[qr1];
    const int colb = (lane & 3) * 2;

    float o[16][4];
#pragma unroll
    for (int j = 0; j < 16; j++)
#pragma unroll
        for (int k = 0; k < 4; k++) o[j][k] = 0.f;
    float m0 = -1e30f, m1 = -1e30f, l0 = 0.f, l1 = 0.f;

    for (int t = 0; t < ntile; t++) {
        const int k0 = t * 64;
        const int buf = t & 1;
        if (t + 1 < ntile) { prefetch(t + 1); CP_WAIT1(); }
        else               { CP_WAIT0(); }
        __syncthreads();

        float sf[8][4];
#pragma unroll
        for (int j = 0; j < 8; j++)
#pragma unroll
            for (int k = 0; k < 4; k++) sf[j][k] = 0.f;

        const uint32_t kb = sb + buf * AT_KB;
#pragma unroll
        for (int ks = 0; ks < 8; ks++) {
            uint32_t bk[4][4];
#pragma unroll
            for (int np = 0; np < 4; np++) {
                uint32_t addr = kb + (np * 16 + ((lane >> 4) << 3) + (lane & 7)) * ATSTR +
                                (ks * 16 + ((lane >> 3) & 1) * 8) * 2;
                ldm_x4(bk[np], addr);
            }
#pragma unroll
            for (int np = 0; np < 4; np++)
#pragma unroll
                for (int s = 0; s < 2; s++)
                    mma_f16(sf[np * 2 + s], qf[ks], bk[np][2 * s], bk[np][2 * s + 1]);
        }

        const int* kc = (const int*)(sm + AT_MC) + buf * 64;
#pragma unroll
        for (int j = 0; j < 8; j++) {
            int c0 = j * 8 + colb, c1 = c0 + 1;
            int kp0 = k0 + c0, kp1 = k0 + c1;
            int kc0 = kc[c0], kc1 = kc[c1];
            if (!(kp0 <= qr0 && kc0 == qseg0)) sf[j][0] = -1e30f;
            if (!(kp1 <= qr0 && kc1 == qseg0)) sf[j][1] = -1e30f;
            if (!(kp0 <= qr1 && kc0 == qseg1)) sf[j][2] = -1e30f;
            if (!(kp1 <= qr1 && kc1 == qseg1)) sf[j][3] = -1e30f;
        }

        float mx0 = -1e30f, mx1 = -1e30f;
#pragma unroll
        for (int j = 0; j < 8; j++) {
            mx0 = fmaxf(mx0, fmaxf(sf[j][0], sf[j][1]));
            mx1 = fmaxf(mx1, fmaxf(sf[j][2], sf[j][3]));
        }
        mx0 = fmaxf(mx0, __shfl_xor_sync(0xffffffffu, mx0, 1));
        mx0 = fmaxf(mx0, __shfl_xor_sync(0xffffffffu, mx0, 2));
        mx1 = fmaxf(mx1, __shfl_xor_sync(0xffffffffu, mx1, 1));
        mx1 = fmaxf(mx1, __shfl_xor_sync(0xffffffffu, mx1, 2));
        float mn0 = fmaxf(m0, mx0), mn1 = fmaxf(m1, mx1);
        float a0 = __expf(m0 - mn0), a1 = __expf(m1 - mn1);
        m0 = mn0; m1 = mn1;
        float s0 = 0.f, s1 = 0.f;
#pragma unroll
        for (int j = 0; j < 8; j++) {
            sf[j][0] = __expf(sf[j][0] - mn0);
            sf[j][1] = __expf(sf[j][1] - mn0);
            sf[j][2] = __expf(sf[j][2] - mn1);
            sf[j][3] = __expf(sf[j][3] - mn1);
            s0 += sf[j][0] + sf[j][1];
            s1 += sf[j][2] + sf[j][3];
        }
        s0 += __shfl_xor_sync(0xffffffffu, s0, 1);
        s0 += __shfl_xor_sync(0xffffffffu, s0, 2);
        s1 += __shfl_xor_sync(0xffffffffu, s1, 1);
        s1 += __shfl_xor_sync(0xffffffffu, s1, 2);
        l0 = l0 * a0 + s0;
        l1 = l1 * a1 + s1;
#pragma unroll
        for (int j = 0; j < 16; j++) {
            o[j][0] *= a0; o[j][1] *= a0;
            o[j][2] *= a1; o[j][3] *= a1;
        }

        uint32_t pa[4][4];
#pragma unroll
        for (int kk = 0; kk < 4; kk++) {
            pa[kk][0] = h2_as_u32(__floats2half2_rn(sf[2 * kk][0], sf[2 * kk][1]));
            pa[kk][1] = h2_as_u32(__floats2half2_rn(sf[2 * kk][2], sf[2 * kk][3]));
            pa[kk][2] = h2_as_u32(__floats2half2_rn(sf[2 * kk + 1][0], sf[2 * kk + 1][1]));
            pa[kk][3] = h2_as_u32(__floats2half2_rn(sf[2 * kk + 1][2], sf[2 * kk + 1][3]));
        }

        const uint32_t vb = sb + AT_V + buf * AT_KB;
#pragma unroll
        for (int ks = 0; ks < 4; ks++) {
            uint32_t bv[8][4];
#pragma unroll
            for (int nb = 0; nb < 8; nb++) {
                uint32_t addr = vb + (ks * 16 + (lane & 15)) * ATSTR +
                                (nb * 16 + (lane >> 4) * 8) * 2;
                ldm_x4_t(bv[nb], addr);
            }
#pragma unroll
            for (int nb = 0; nb < 8; nb++)
#pragma unroll
                for (int s = 0; s < 2; s++)
                    mma_f16(o[nb * 2 + s], pa[ks], bv[nb][2 * s], bv[nb][2 * s + 1]);
        }
        __syncthreads();
    }

    float inv0 = (l0 > 0.f) ? 1.f / l0 : 0.f;
    float inv1 = (l1 > 0.f) ? 1.f / l1 : 0.f;
#pragma unroll
    for (int j = 0; j < 16; j++) {
        int col = h * HD + j * 8 + colb;
        *(__half2*)(g_Ah + (size_t)qr0 * 2048 + col) =
            __floats2half2_rn(o[j][0] * inv0, o[j][1] * inv0);
        *(__half2*)(g_Ah + (size_t)qr1 * 2048 + col) =
            __floats2half2_rn(o[j][2] * inv1, o[j][3] * inv1);
    }
}

// ---------------------------------------------------------------------------
// Host launcher
// ---------------------------------------------------------------------------
extern "C" void kernel_launch(void* const* d_in, const int* in_sizes, int n_in,
                              void* d_out, int out_size)
{
    const float* X     = (const float*)d_in[0];
    const int*   amask = (const int*)d_in[1];
    const int*   segs  = (const int*)d_in[2];
    const int*   pos   = (const int*)d_in[3];
    const float* Wq    = (const float*)d_in[4];
    const float* Wk    = (const float*)d_in[5];
    const float* Wv    = (const float*)d_in[6];
    const float* Wo    = (const float*)d_in[7];
    float* out = (float*)d_out;

    const int S   = in_sizes[3];
    const int H   = in_sizes[0] / S;        // 2048

    __half *Ah, *Bh;
    cudaGetSymbolAddress((void**)&Ah, g_Ah);
    cudaGetSymbolAddress((void**)&Bh, g_Bh);

    const int gemm_smem = 3 * STAGEB;   // 96KB
    cudaFuncSetAttribute(gemm_mma, cudaFuncAttributeMaxDynamicSharedMemorySize,
                         gemm_smem);
    cudaFuncSetAttribute(attn_mma, cudaFuncAttributeMaxDynamicSharedMemorySize,
                         AT_SMEM);

    const int n4 = (S * H) / 4;
    // X -> fp16
    cvt_h<<<(n4 + 255) / 256, 256>>>(X, Ah, n4);
    // pack Wq|Wk|Wv transposed (x256) into B[3072][2048] (single launch)
    cvt_T_h3<<<dim3(3072 / 32, H / 32), dim3(32, 8)>>>(Wq, Wk, Wv);
    rope_tab<<<(S * 64 + 255) / 256, 256>>>(pos, S);

    // fused QKV GEMM with rope/fp16 epilogue
    gemm_mma<<<dim3(3072 / 128, S / 128), 512, gemm_smem>>>(nullptr, 3072, 1);

    // fp16 tensor-core flash attention (writes fp16 A to g_Ah)
    attn_mma<<<dim3(S / 64, NH), 128, AT_SMEM>>>(amask, segs);

    // out = A @ Wo / 256
    cvt_T_h<<<dim3(H / 32, H / 32), dim3(32, 8)>>>(Wo, Bh, H, H);
    gemm_mma<<<dim3(H / 128, S / 128), 512, gemm_smem>>>(out, H, 0);
}

// round 9
// speedup vs baseline: 8.7238x; 1.0748x over previous
#include <cuda_runtime.h>
#include <cuda_bf16.h>
#include <cuda_fp16.h>
#include <math.h>
#include <stdint.h>

#define NH   16
#define NKV  4
#define HD   128
#define SMAX 2048
#define KDIM 2048

// ---------------- scratch (device globals; no allocation allowed) ----------
__device__ __align__(256) __half g_Ah[SMAX * KDIM];
__device__ __align__(256) __half g_Bh[3072 * KDIM];
__device__ __align__(256) __half h_Q[SMAX * NH * HD];
__device__ __align__(256) __half h_K[SMAX * NKV * HD];
__device__ __align__(256) __half h_V[SMAX * NKV * HD];
__device__ __align__(256) float2 g_rope[SMAX * 64];

#define WSCALE 256.0f
#define INVW   0.00390625f

// ---------------- helpers --------------------------------------------------
__device__ __forceinline__ uint32_t smem_u32(const void* p) {
    uint32_t a;
    asm("{ .reg .u64 t; cvta.to.shared.u64 t, %1; cvt.u32.u64 %0, t; }"
        : "=r"(a) : "l"(p));
    return a;
}
__device__ __forceinline__ uint32_t h2_as_u32(__half2 h) {
    return *reinterpret_cast<uint32_t*>(&h);
}
__device__ __forceinline__ void ldm_x4(uint32_t* r, uint32_t addr) {
    asm volatile("ldmatrix.sync.aligned.m8n8.x4.shared.b16 {%0,%1,%2,%3}, [%4];"
                 : "=r"(r[0]), "=r"(r[1]), "=r"(r[2]), "=r"(r[3]) : "r"(addr));
}
__device__ __forceinline__ void ldm_x4_t(uint32_t* r, uint32_t addr) {
    asm volatile("ldmatrix.sync.aligned.m8n8.x4.trans.shared.b16 {%0,%1,%2,%3}, [%4];"
                 : "=r"(r[0]), "=r"(r[1]), "=r"(r[2]), "=r"(r[3]) : "r"(addr));
}
__device__ __forceinline__ void mma_f16(float* d, const uint32_t* a,
                                        uint32_t b0, uint32_t b1) {
    asm volatile(
        "mma.sync.aligned.m16n8k16.row.col.f32.f16.f16.f32 "
        "{%0,%1,%2,%3}, {%4,%5,%6,%7}, {%8,%9}, {%0,%1,%2,%3};"
        : "+f"(d[0]), "+f"(d[1]), "+f"(d[2]), "+f"(d[3])
        : "r"(a[0]), "r"(a[1]), "r"(a[2]), "r"(a[3]), "r"(b0), "r"(b1));
}
__device__ __forceinline__ void cp_async16(uint32_t dst, const void* src) {
    asm volatile("cp.async.cg.shared.global [%0], [%1], 16;"
                 :: "r"(dst), "l"(src) : "memory");
}
#define CP_COMMIT() asm volatile("cp.async.commit_group;" ::: "memory")
#define CP_WAIT0()  asm volatile("cp.async.wait_group 0;" ::: "memory")
#define CP_WAIT1()  asm volatile("cp.async.wait_group 1;" ::: "memory")

// ---------------------------------------------------------------------------
// fp16 GEMM via mma.sync. A = g_Ah [2048][2048], B = g_Bh [N][2048] (x256).
// CTA tile 128(M)x64(N), 256 threads (8 warps, 4x2 of 32x32), BK=64,
// 3-stage cp.async pipeline, 2 CTAs/SM ping-pong.
// qkv=0: C fp32 (x 1/256).  qkv=1: fused rope/scale/fp16 epilogue -> h_Q/K/V.
// ---------------------------------------------------------------------------
#define NC      (KDIM / 64)
#define STAGEB  24576          // A 16KB + B 8KB
#define OFF_B   16384

__global__ __launch_bounds__(256, 2) void gemm_mma(float* __restrict__ C,
                                                   int N, int qkv)
{
    extern __shared__ char smem[];
    const uint32_t sb = smem_u32(smem);
    const int tid = threadIdx.x, lane = tid & 31, wid = tid >> 5;
    const int m0 = blockIdx.y * 128, n0 = blockIdx.x * 64;
    const int wm = (wid >> 1) * 32, wn = (wid & 1) * 32;

    auto load_chunk = [&](int c, int buf) {
        uint32_t base = sb + buf * STAGEB;
        // A: 128 rows x 64 halves (16KB) -> 4 iterations
#pragma unroll
        for (int it = 0; it < 4; it++) {
            int idx = tid + it * 256;
            int row = idx >> 3, ch = idx & 7;
            cp_async16(base + row * 128 + ((ch ^ (row & 7)) << 4),
                       g_Ah + (size_t)(m0 + row) * KDIM + c * 64 + ch * 8);
        }
        // B: 64 rows x 64 halves (8KB) -> 2 iterations
#pragma unroll
        for (int it = 0; it < 2; it++) {
            int idx = tid + it * 256;
            int row = idx >> 3, ch = idx & 7;
            cp_async16(base + OFF_B + row * 128 + ((ch ^ (row & 7)) << 4),
                       g_Bh + (size_t)(n0 + row) * KDIM + c * 64 + ch * 8);
        }
        CP_COMMIT();
    };

    const int arow = wm + (lane & 15);
    const int cA   = lane >> 4;
    const int brow = wn + ((lane >> 4) << 3) + (lane & 7);
    const int cB   = (lane >> 3) & 1;

    float d[2][4][4];
#pragma unroll
    for (int i = 0; i < 2; i++)
#pragma unroll
        for (int j = 0; j < 4; j++)
#pragma unroll
            for (int k = 0; k < 4; k++) d[i][j][k] = 0.f;

    load_chunk(0, 0);
    load_chunk(1, 1);

    for (int c = 0; c < NC; c++) {
        if (c < NC - 1) CP_WAIT1(); else CP_WAIT0();
        __syncthreads();
        if (c + 2 < NC) load_chunk(c + 2, (c + 2) % 3);

        const uint32_t base = sb + (c % 3) * STAGEB;
#pragma unroll
        for (int ks = 0; ks < 4; ks++) {
            uint32_t a[2][4], b[2][4];
#pragma unroll
            for (int mt = 0; mt < 2; mt++) {
                int row = arow + mt * 16;
                ldm_x4(a[mt], base + row * 128 + (((ks * 2 + cA) ^ (row & 7)) << 4));
            }
#pragma unroll
            for (int np = 0; np < 2; np++) {
                int row = brow + np * 16;
                ldm_x4(b[np], base + OFF_B + row * 128 +
                              (((ks * 2 + cB) ^ (row & 7)) << 4));
            }
#pragma unroll
            for (int mt = 0; mt < 2; mt++)
#pragma unroll
                for (int np = 0; np < 2; np++)
#pragma unroll
                    for (int s = 0; s < 2; s++)
                        mma_f16(d[mt][np * 2 + s], a[mt], b[np][2 * s], b[np][2 * s + 1]);
        }
        __syncthreads();
    }

    const int colb = (lane & 3) * 2;
    if (!qkv) {
#pragma unroll
        for (int mt = 0; mt < 2; mt++) {
            int r = m0 + wm + mt * 16 + (lane >> 2);
#pragma unroll
            for (int nt = 0; nt < 4; nt++) {
                int col = n0 + wn + nt * 8 + colb;
                *(float2*)(C + (size_t)r * N + col) =
                    make_float2(d[mt][nt][0] * INVW, d[mt][nt][1] * INVW);
                *(float2*)(C + (size_t)(r + 8) * N + col) =
                    make_float2(d[mt][nt][2] * INVW, d[mt][nt][3] * INVW);
            }
        }
    } else {
        const int mode = (n0 < 2048) ? 0 : (n0 < 2560 ? 1 : 2);
        const float qs = 0.0883883476483184f * INVW;
#pragma unroll
        for (int mt = 0; mt < 2; mt++) {
            int r = m0 + wm + mt * 16 + (lane >> 2);
#pragma unroll
            for (int nt = 0; nt < 4; nt++) {
                int col = n0 + wn + nt * 8 + colb;
                float c00 = d[mt][nt][0], c01 = d[mt][nt][1];
                float c10 = d[mt][nt][2], c11 = d[mt][nt][3];
                if (mode == 2) {
                    int cv = col - 2560;
                    *(__half2*)(h_V + (size_t)r * 512 + cv) =
                        __floats2half2_rn(c00 * INVW, c01 * INVW);
                    *(__half2*)(h_V + (size_t)(r + 8) * 512 + cv) =
                        __floats2half2_rn(c10 * INVW, c11 * INVW);
                } else {
                    int cl = (mode == 0) ? col : col - 2048;
                    int i = (cl & 127) >> 1;
                    float2 t0 = g_rope[r * 64 + i];
                    float2 t1 = g_rope[(r + 8) * 64 + i];
                    float s = (mode == 0) ? qs : INVW;
                    float o00 = (c00 * t0.x - c01 * t0.y) * s;
                    float o01 = (c00 * t0.y + c01 * t0.x) * s;
                    float o10 = (c10 * t1.x - c11 * t1.y) * s;
                    float o11 = (c10 * t1.y + c11 * t1.x) * s;
                    if (mode == 0) {
                        *(__half2*)(h_Q + (size_t)r * 2048 + cl)       = __floats2half2_rn(o00, o01);
                        *(__half2*)(h_Q + (size_t)(r + 8) * 2048 + cl) = __floats2half2_rn(o10, o11);
                    } else {
                        *(__half2*)(h_K + (size_t)r * 512 + cl)       = __floats2half2_rn(o00, o01);
                        *(__half2*)(h_K + (size_t)(r + 8) * 512 + cl) = __floats2half2_rn(o10, o11);
                    }
                }
            }
        }
    }
}

// ---------------------------------------------------------------------------
// conversions
// ---------------------------------------------------------------------------
__global__ void cvt_h(const float* __restrict__ in, __half* __restrict__ out, int n4)
{
    int i = blockIdx.x * blockDim.x + threadIdx.x;
    if (i >= n4) return;
    float4 v = ((const float4*)in)[i];
    uint2 u;
    u.x = h2_as_u32(__floats2half2_rn(v.x, v.y));
    u.y = h2_as_u32(__floats2half2_rn(v.z, v.w));
    ((uint2*)out)[i] = u;
}

// single-matrix transpose+convert (used for Wo)
__global__ void cvt_T_h(const float* __restrict__ W, __half* __restrict__ out,
                        int K, int N)
{
    __shared__ float t[32][33];
    int x = blockIdx.x * 32 + threadIdx.x;
    int y = blockIdx.y * 32 + threadIdx.y;
#pragma unroll
    for (int j = 0; j < 32; j += 8)
        t[threadIdx.y + j][threadIdx.x] = W[(size_t)(y + j) * N + x];
    __syncthreads();
    int x2 = blockIdx.y * 32 + threadIdx.x;
    int y2 = blockIdx.x * 32 + threadIdx.y;
#pragma unroll
    for (int j = 0; j < 32; j += 8)
        out[(size_t)(y2 + j) * K + x2] = __float2half_rn(t[threadIdx.x][threadIdx.y + j] * WSCALE);
}

// merged Wq|Wk|Wv transpose+convert into g_Bh[3072][2048]
__global__ void cvt_T_h3(const float* __restrict__ Wq, const float* __restrict__ Wk,
                         const float* __restrict__ Wv)
{
    __shared__ float t[32][33];
    int bc = blockIdx.x * 32;
    const float* W; int n0, Nw;
    if (bc < 2048)      { W = Wq; n0 = 0;    Nw = 2048; }
    else if (bc < 2560) { W = Wk; n0 = 2048; Nw = 512;  }
    else                { W = Wv; n0 = 2560; Nw = 512;  }
    int x = bc - n0 + threadIdx.x;
    int y = blockIdx.y * 32 + threadIdx.y;
#pragma unroll
    for (int j = 0; j < 32; j += 8)
        t[threadIdx.y + j][threadIdx.x] = W[(size_t)(y + j) * Nw + x];
    __syncthreads();
    int x2 = blockIdx.y * 32 + threadIdx.x;
    int y2 = bc + threadIdx.y;
#pragma unroll
    for (int j = 0; j < 32; j += 8)
        g_Bh[(size_t)(y2 + j) * KDIM + x2] =
            __float2half_rn(t[threadIdx.x][threadIdx.y + j] * WSCALE);
}

__global__ void rope_tab(const int* __restrict__ pos, int S)
{
    int idx = blockIdx.x * blockDim.x + threadIdx.x;
    if (idx >= S * 64) return;
    int i = idx & 63, s = idx >> 6;
    float freq = exp2f(-(float)(2 * i) * (1.0f / 128.0f) * 13.287712379549449f);
    float ang = (float)pos[s] * freq;
    float sn, cs;
    sincosf(ang, &sn, &cs);
    g_rope[idx] = make_float2(cs, sn);
}

// ---------------------------------------------------------------------------
// fp16 mma.sync flash attention. 128 threads (4 warps), BQ=64, KV tiles of 64.
// Q staged in K-buffer-1 region; 3 CTAs/SM.
// Epilogue writes fp16 A directly into g_Ah.
// ---------------------------------------------------------------------------
#define ATSTR 272
#define AT_KB 17408
#define AT_V  34816
#define AT_MC 69632
#define AT_SMEM 70144

__global__ __launch_bounds__(128, 3) void attn_mma(
    const int* __restrict__ amask, const int* __restrict__ segs)
{
    extern __shared__ char sm[];
    const uint32_t sb = smem_u32(sm);
    const int tid = threadIdx.x, lane = tid & 31, wid = tid >> 5;
    const int h = blockIdx.y;
    const int qb = (int)gridDim.x - 1 - (int)blockIdx.x;
    const int q0 = qb * 64;
    const int kvh = h >> 2;
    const int ntile = qb + 1;

    auto prefetch = [&](int t) {
        int k0 = t * 64;
        int buf = t & 1;
#pragma unroll
        for (int it = 0; it < 8; it++) {
            int idx = tid + it * 128;
            int row = idx >> 4, ch = idx & 15;
            cp_async16(sb + buf * AT_KB + row * ATSTR + ch * 16,
                       h_K + ((size_t)(k0 + row) * NKV + kvh) * HD + ch * 8);
            cp_async16(sb + AT_V + buf * AT_KB + row * ATSTR + ch * 16,
                       h_V + ((size_t)(k0 + row) * NKV + kvh) * HD + ch * 8);
        }
        if (tid < 64) {
            int a = amask[k0 + tid];
            ((int*)(sm + AT_MC))[buf * 64 + tid] =
                (a > 0) ? segs[k0 + tid] : 0x7fffffff;
        }
        CP_COMMIT();
    };

#pragma unroll
    for (int it = 0; it < 8; it++) {
        int idx = tid + it * 128;
        int row = idx >> 4, ch = idx & 15;
        cp_async16(sb + AT_KB + row * ATSTR + ch * 16,
                   h_Q + ((size_t)(q0 + row) * NH + h) * HD + ch * 8);
    }
    prefetch(0);
    CP_WAIT0();
    __syncthreads();

    uint32_t qf[8][4];
#pragma unroll
    for (int ks = 0; ks < 8; ks++) {
        uint32_t addr = sb + AT_KB + (wid * 16 + (lane & 15)) * ATSTR +
                        (ks * 16 + (lane >> 4) * 8) * 2;
        ldm_x4(qf[ks], addr);
    }
    __syncthreads();

    const int qr0 = q0 + wid * 16 + (lane >> 2);
    const int qr1 = qr0 + 8;
    const int qseg0 = segs[qr0];
    const int qseg1 = segs[qr1];
    const int colb = (lane & 3) * 2;

    float o[16][4];
#pragma unroll
    for (int j = 0; j < 16; j++)
#pragma unroll
        for (int k = 0; k < 4; k++) o[j][k] = 0.f;
    float m0 = -1e30f, m1 = -1e30f, l0 = 0.f, l1 = 0.f;

    for (int t = 0; t < ntile; t++) {
        const int k0 = t * 64;
        const int buf = t & 1;
        if (t + 1 < ntile) { prefetch(t + 1); CP_WAIT1(); }
        else               { CP_WAIT0(); }
        __syncthreads();

        float sf[8][4];
#pragma unroll
        for (int j = 0; j < 8; j++)
#pragma unroll
            for (int k = 0; k < 4; k++) sf[j][k] = 0.f;

        const uint32_t kb = sb + buf * AT_KB;
#pragma unroll
        for (int ks = 0; ks < 8; ks++) {
            uint32_t bk[4][4];
#pragma unroll
            for (int np = 0; np < 4; np++) {
                uint32_t addr = kb + (np * 16 + ((lane >> 4) << 3) + (lane & 7)) * ATSTR +
                                (ks * 16 + ((lane >> 3) & 1) * 8) * 2;
                ldm_x4(bk[np], addr);
            }
#pragma unroll
            for (int np = 0; np < 4; np++)
#pragma unroll
                for (int s = 0; s < 2; s++)
                    mma_f16(sf[np * 2 + s], qf[ks], bk[np][2 * s], bk[np][2 * s + 1]);
        }

        const int* kc = (const int*)(sm + AT_MC) + buf * 64;
#pragma unroll
        for (int j = 0; j < 8; j++) {
            int c0 = j * 8 + colb, c1 = c0 + 1;
            int kp0 = k0 + c0, kp1 = k0 + c1;
            int kc0 = kc[c0], kc1 = kc[c1];
            if (!(kp0 <= qr0 && kc0 == qseg0)) sf[j][0] = -1e30f;
            if (!(kp1 <= qr0 && kc1 == qseg0)) sf[j][1] = -1e30f;
            if (!(kp0 <= qr1 && kc0 == qseg1)) sf[j][2] = -1e30f;
            if (!(kp1 <= qr1 && kc1 == qseg1)) sf[j][3] = -1e30f;
        }

        float mx0 = -1e30f, mx1 = -1e30f;
#pragma unroll
        for (int j = 0; j < 8; j++) {
            mx0 = fmaxf(mx0, fmaxf(sf[j][0], sf[j][1]));
            mx1 = fmaxf(mx1, fmaxf(sf[j][2], sf[j][3]));
        }
        mx0 = fmaxf(mx0, __shfl_xor_sync(0xffffffffu, mx0, 1));
        mx0 = fmaxf(mx0, __shfl_xor_sync(0xffffffffu, mx0, 2));
        mx1 = fmaxf(mx1, __shfl_xor_sync(0xffffffffu, mx1, 1));
        mx1 = fmaxf(mx1, __shfl_xor_sync(0xffffffffu, mx1, 2));
        float mn0 = fmaxf(m0, mx0), mn1 = fmaxf(m1, mx1);
        float a0 = __expf(m0 - mn0), a1 = __expf(m1 - mn1);
        m0 = mn0; m1 = mn1;
        float s0 = 0.f, s1 = 0.f;
#pragma unroll
        for (int j = 0; j < 8; j++) {
            sf[j][0] = __expf(sf[j][0] - mn0);
            sf[j][1] = __expf(sf[j][1] - mn0);
            sf[j][2] = __expf(sf[j][2] - mn1);
            sf[j][3] = __expf(sf[j][3] - mn1);
            s0 += sf[j][0] + sf[j][1];
            s1 += sf[j][2] + sf[j][3];
        }
        s0 += __shfl_xor_sync(0xffffffffu, s0, 1);
        s0 += __shfl_xor_sync(0xffffffffu, s0, 2);
        s1 += __shfl_xor_sync(0xffffffffu, s1, 1);
        s1 += __shfl_xor_sync(0xffffffffu, s1, 2);
        l0 = l0 * a0 + s0;
        l1 = l1 * a1 + s1;
#pragma unroll
        for (int j = 0; j < 16; j++) {
            o[j][0] *= a0; o[j][1] *= a0;
            o[j][2] *= a1; o[j][3] *= a1;
        }

        uint32_t pa[4][4];
#pragma unroll
        for (int kk = 0; kk < 4; kk++) {
            pa[kk][0] = h2_as_u32(__floats2half2_rn(sf[2 * kk][0], sf[2 * kk][1]));
            pa[kk][1] = h2_as_u32(__floats2half2_rn(sf[2 * kk][2], sf[2 * kk][3]));
            pa[kk][2] = h2_as_u32(__floats2half2_rn(sf[2 * kk + 1][0], sf[2 * kk + 1][1]));
            pa[kk][3] = h2_as_u32(__floats2half2_rn(sf[2 * kk + 1][2], sf[2 * kk + 1][3]));
        }

        const uint32_t vb = sb + AT_V + buf * AT_KB;
#pragma unroll
        for (int ks = 0; ks < 4; ks++) {
            uint32_t bv[8][4];
#pragma unroll
            for (int nb = 0; nb < 8; nb++) {
                uint32_t addr = vb + (ks * 16 + (lane & 15)) * ATSTR +
                                (nb * 16 + (lane >> 4) * 8) * 2;
                ldm_x4_t(bv[nb], addr);
            }
#pragma unroll
            for (int nb = 0; nb < 8; nb++)
#pragma unroll
                for (int s = 0; s < 2; s++)
                    mma_f16(o[nb * 2 + s], pa[ks], bv[nb][2 * s], bv[nb][2 * s + 1]);
        }
        __syncthreads();
    }

    float inv0 = (l0 > 0.f) ? 1.f / l0 : 0.f;
    float inv1 = (l1 > 0.f) ? 1.f / l1 : 0.f;
#pragma unroll
    for (int j = 0; j < 16; j++) {
        int col = h * HD + j * 8 + colb;
        *(__half2*)(g_Ah + (size_t)qr0 * 2048 + col) =
            __floats2half2_rn(o[j][0] * inv0, o[j][1] * inv0);
        *(__half2*)(g_Ah + (size_t)qr1 * 2048 + col) =
            __floats2half2_rn(o[j][2] * inv1, o[j][3] * inv1);
    }
}

// ---------------------------------------------------------------------------
// Host launcher
// ---------------------------------------------------------------------------
extern "C" void kernel_launch(void* const* d_in, const int* in_sizes, int n_in,
                              void* d_out, int out_size)
{
    const float* X     = (const float*)d_in[0];
    const int*   amask = (const int*)d_in[1];
    const int*   segs  = (const int*)d_in[2];
    const int*   pos   = (const int*)d_in[3];
    const float* Wq    = (const float*)d_in[4];
    const float* Wk    = (const float*)d_in[5];
    const float* Wv    = (const float*)d_in[6];
    const float* Wo    = (const float*)d_in[7];
    float* out = (float*)d_out;

    const int S   = in_sizes[3];
    const int H   = in_sizes[0] / S;        // 2048

    __half *Ah, *Bh;
    cudaGetSymbolAddress((void**)&Ah, g_Ah);
    cudaGetSymbolAddress((void**)&Bh, g_Bh);

    const int gemm_smem = 3 * STAGEB;   // 72KB
    cudaFuncSetAttribute(gemm_mma, cudaFuncAttributeMaxDynamicSharedMemorySize,
                         gemm_smem);
    cudaFuncSetAttribute(attn_mma, cudaFuncAttributeMaxDynamicSharedMemorySize,
                         AT_SMEM);

    const int n4 = (S * H) / 4;
    cvt_h<<<(n4 + 255) / 256, 256>>>(X, Ah, n4);
    cvt_T_h3<<<dim3(3072 / 32, H / 32), dim3(32, 8)>>>(Wq, Wk, Wv);
    rope_tab<<<(S * 64 + 255) / 256, 256>>>(pos, S);

    // fused QKV GEMM with rope/fp16 epilogue
    gemm_mma<<<dim3(3072 / 64, S / 128), 256, gemm_smem>>>(nullptr, 3072, 1);

    // fp16 tensor-core flash attention (writes fp16 A to g_Ah)
    attn_mma<<<dim3(S / 64, NH), 128, AT_SMEM>>>(amask, segs);

    // out = A @ Wo / 256
    cvt_T_h<<<dim3(H / 32, H / 32), dim3(32, 8)>>>(Wo, Bh, H, H);
    gemm_mma<<<dim3(H / 64, S / 128), 256, gemm_smem>>>(out, H, 0);
}